// round 11
// baseline (speedup 1.0000x reference)
#include <cuda_runtime.h>
#include <cuda_fp16.h>
#include <cstdint>

#define S_LEN 200
#define BATCH 1024
#define HID   128
#define VOCAB 100000
#define GNB   4          // batch rows per RNN work group
#define NGRP  (BATCH / GNB)

// ---------------- scratch (device globals; no allocation) ----------------
__device__ __align__(16) float    g_E[(size_t)S_LEN * BATCH * HID];   // compacted E (fp32)
__device__ __align__(16) float    g_w[(size_t)S_LEN * BATCH];
__device__ float                  g_wsum[BATCH];
__device__ __align__(16) uint32_t g_outpu_h[(size_t)BATCH * HID];     // fp16x2 [B,256]
__device__ __align__(16) uint32_t g_Wenc_h[(size_t)VOCAB * HID / 2];  // 25.6 MB fp16
__device__ __align__(16) uint32_t g_Wih_h[(size_t)HID * HID / 2];
__device__ __align__(16) uint32_t g_Wfc_h[(size_t)VOCAB * HID];       // 51.2 MB fp16 (V x 256)
__device__ int                    g_perm[BATCH];   // batch order, length descending
__device__ int                    g_slen[BATCH];   // sorted lengths
__device__ int                    g_ctr;           // work-steal counter
__device__ int                    g_off[S_LEN + 1];// compact row offsets
__device__ int                    g_Mpad;          // padded compact row count
__device__ int                    g_gidx[(size_t)S_LEN * BATCH]; // vocab id per compact row

// ---------------- helpers ----------------
__device__ __forceinline__ void cp16(void* smem, const void* gmem)
{
    uint32_t s = (uint32_t)__cvta_generic_to_shared(smem);
    asm volatile("cp.async.cg.shared.global [%0], [%1], 16;" :: "r"(s), "l"(gmem));
}
__device__ __forceinline__ void cp_commit() { asm volatile("cp.async.commit_group;"); }
template <int W> __device__ __forceinline__ void cp_wait()
{
    asm volatile("cp.async.wait_group %0;" :: "n"(W));
}
__device__ __forceinline__ uint32_t f2h2(float lo, float hi)
{
    __half2 h = __floats2half2_rn(lo, hi);   // lo -> low 16 bits
    return *(uint32_t*)&h;
}

// ---------------- kernel 0: fp32 -> fp16 (RN) streaming convert -----------------
// reads float4 (4 floats), writes uint2 (4 halves)
__global__ void cvt_fp16_kernel(const float4* __restrict__ in,
                                uint2* __restrict__ out, int n4)
{
    int i = blockIdx.x * blockDim.x + threadIdx.x;
    if (i < n4) {
        float4 v = in[i];
        out[i] = make_uint2(f2h2(v.x, v.y), f2h2(v.z, v.w));
    }
}

// ---------------- kernel 0b: sort batch rows by length (descending) ------------
__global__ void __launch_bounds__(1024)
sort_len_kernel(const int* __restrict__ length,
                int* __restrict__ perm, int* __restrict__ slen, int* __restrict__ ctr)
{
    __shared__ unsigned key[BATCH];
    int tid = threadIdx.x;
    key[tid] = ((unsigned)(200 - length[tid]) << 10) | (unsigned)tid;
    if (tid == 0) *ctr = 0;
    __syncthreads();
#pragma unroll 1
    for (int k = 2; k <= BATCH; k <<= 1) {
#pragma unroll 1
        for (int j = k >> 1; j > 0; j >>= 1) {
            int ixj = tid ^ j;
            if (ixj > tid) {
                unsigned a = key[tid], b = key[ixj];
                bool up = ((tid & k) == 0);
                if ((a > b) == up) { key[tid] = b; key[ixj] = a; }
            }
            __syncthreads();
        }
    }
    perm[tid] = (int)(key[tid] & 1023u);
    slen[tid] = 200 - (int)(key[tid] >> 10);
}

// ---------------- kernel 0c: compact-row offsets (1 small CTA) -----------------
__global__ void __launch_bounds__(256)
build_offsets_kernel(const int* __restrict__ slen, int* __restrict__ off,
                     int* __restrict__ Mpad)
{
    __shared__ int cnt[S_LEN];
    int s = threadIdx.x;
    if (s < S_LEN) {
        int lo = 0, hi = BATCH;           // count of slen[j] > s (sorted desc)
        while (lo < hi) { int mid = (lo + hi) >> 1; if (slen[mid] > s) lo = mid + 1; else hi = mid; }
        cnt[s] = lo;
    }
    __syncthreads();
    if (s == 0) {
        int acc = 0;
        for (int i = 0; i < S_LEN; i++) { off[i] = acc; acc += cnt[i]; }
        off[S_LEN] = acc;
        *Mpad = (acc + 127) & ~127;
    }
}

// ---------------- kernel 0d: fill gather indices for compacted rows ------------
__global__ void __launch_bounds__(256)
fill_gidx_kernel(const int* __restrict__ x, const int* __restrict__ perm,
                 const int* __restrict__ off, const int* __restrict__ Mpad,
                 int* __restrict__ gidx)
{
    int s = blockIdx.x;
    if (s < S_LEN) {
        int base = off[s], cnt = off[s + 1] - base;
        for (int j = threadIdx.x; j < cnt; j += blockDim.x)
            gidx[base + j] = x[(size_t)s * BATCH + perm[j]];
    } else {
        int total = off[S_LEN], mp = *Mpad;
        for (int i = threadIdx.x; i < mp - total; i += blockDim.x)
            gidx[total + i] = 0;
    }
}

// ---------------- kernel 1: pooling weights (1 block per batch, s-parallel) ----
__global__ void __launch_bounds__(256)
pool_weights_kernel(const float* __restrict__ t,
                    const float* __restrict__ sxy,
                    const int* __restrict__ length,
                    float* __restrict__ w,
                    float* __restrict__ wsum)
{
    int b   = blockIdx.x;
    int s   = threadIdx.x;
    int lane = s & 31, warp = s >> 5;
    __shared__ float red[8];
    __shared__ float bc[3];

    int len = length[b];
    if (s == 0) {
        bc[0] = t[(size_t)(len - 1) * BATCH + b];
        float2 sl = *(const float2*)&sxy[((size_t)(len - 1) * BATCH + b) * 2];
        bc[1] = sl.x;
        bc[2] = sl.y;
    }
    __syncthreads();

    const float c1 = 6.28318530717958647692f / 86400.0f;
    const float c2 = 0.1f / 86400.0f;
    float wv = 0.0f;
    if (s < S_LEN) {
        float dt = bc[0] - t[(size_t)s * BATCH + b];
        float2 sv = *(const float2*)&sxy[((size_t)s * BATCH + b) * 2];
        float dx = bc[1] - sv.x, dy = bc[2] - sv.y;
        float ds = sqrtf(dx * dx + dy * dy);
        float ft = (cosf(dt * c1) + 1.0f) * 0.5f * expf(-dt * c2);
        float fs = expf(-ds * 1000.0f);
        wv = (s < len) ? (ft * fs + 1e-10f) : 0.0f;
        w[(size_t)s * BATCH + b] = wv;
    }
#pragma unroll
    for (int off = 16; off > 0; off >>= 1)
        wv += __shfl_down_sync(0xffffffffu, wv, off);
    if (lane == 0) red[warp] = wv;
    __syncthreads();
    if (s < 8) {
        float v = red[s];
#pragma unroll
        for (int off = 4; off > 0; off >>= 1)
            v += __shfl_down_sync(0xffu, v, off);
        if (s == 0) wsum[b] = v;
    }
}

// ---------------- kernel 2/4: fp16 GEMM  C[M,N] = A[M,K]*B[N,K]^T + bias -------
// A,B PRE-CONVERTED fp16, packed as u32 = f16x2 along k (kpair index).
// 3-stage cp.async, 256 threads, 8 warps 2(m)x4(n), warp tile 64x32,
// mma m16n8k16 (fragment kpair indices identical to the tf32 element indices).
// GATHER: row gather via gidx + device-side M bound (dM) early exit.
template <bool GATHER, bool NBOUND>
__global__ void __launch_bounds__(256, 2)
gemm_f16(const uint32_t* __restrict__ A, const int* __restrict__ gidx,
         const int* __restrict__ dM,
         const uint32_t* __restrict__ Bm,
         const float* __restrict__ bias1, const float* __restrict__ bias2,
         float* __restrict__ C, int N, int K)
{
    if (GATHER && (blockIdx.x << 7) >= *dM) return;

    const int PAD = 20;                 // u32 per row (16 data + 4 pad); 20*{0..7}%32 distinct
    const int STG = 128 * PAD;
    extern __shared__ uint32_t smemu[];
    uint32_t* sAs = smemu;              // [A0 A1 A2 | B0 B1 B2]
    uint32_t* sBs = smemu + 3 * STG;

    int tid  = threadIdx.x;
    int lane = tid & 31, warp = tid >> 5;
    int wm = (warp & 1) << 6;           // 0 / 64
    int wn = (warp >> 1) << 5;          // 0 / 32 / 64 / 96
    int g  = lane >> 2, tg = lane & 3;
    int m0 = blockIdx.x * 128;
    int n0 = blockIdx.y * 128;

    int K2 = K >> 1;                    // row stride in u32
    int lrow = tid >> 2;                // 0..63  (q-step covers 64 rows)
    int lc4  = (tid & 3) << 2;          // u32 offset within 16-u32 chunk row

    float acc[4][4][4];
#pragma unroll
    for (int a = 0; a < 4; a++)
#pragma unroll
        for (int b = 0; b < 4; b++)
#pragma unroll
            for (int c = 0; c < 4; c++) acc[a][b][c] = 0.0f;

    auto load_tile = [&](int stage, int k0u) {   // k0u: chunk offset in u32
#pragma unroll
        for (int q = 0; q < 2; q++) {
            int r = q * 64 + lrow;
            long arow = GATHER ? (long)gidx[m0 + r] : (long)(m0 + r);
            cp16(sAs + stage * STG + r * PAD + lc4, A + arow * (long)K2 + k0u + lc4);
            int nrow = n0 + r;
            if (NBOUND && nrow >= N) nrow = N - 1;   // clamp: value unused
            cp16(sBs + stage * STG + r * PAD + lc4, Bm + (long)nrow * K2 + k0u + lc4);
        }
        cp_commit();
    };

    int nChunks = K >> 5;               // 32-k chunks (16 u32 wide)
    load_tile(0, 0);
    if (nChunks > 1) load_tile(1, 16);

    int stage = 0;
    for (int kc = 0; kc < nChunks; kc++) {
        if (kc + 1 < nChunks) cp_wait<1>(); else cp_wait<0>();
        __syncthreads();
        if (kc + 2 < nChunks) {
            int nst = stage + 2; if (nst >= 3) nst -= 3;
            load_tile(nst, (kc + 2) << 4);
        }

        const uint32_t* sA = sAs + stage * STG;
        const uint32_t* sB = sBs + stage * STG;
#pragma unroll
        for (int ks = 0; ks < 2; ks++) {        // two k16 steps per 32-k chunk
            int kk = ks << 3;                   // kpair base: 0 / 8
            uint32_t af[4][4];
            uint32_t bf[4][2];
#pragma unroll
            for (int mf = 0; mf < 4; mf++) {
                int r = wm + (mf << 4);
                af[mf][0] = sA[(r + g)     * PAD + kk + tg];      // rows g,   k 2tg..2tg+1
                af[mf][1] = sA[(r + g + 8) * PAD + kk + tg];      // rows g+8
                af[mf][2] = sA[(r + g)     * PAD + kk + tg + 4];  // k 2tg+8..2tg+9
                af[mf][3] = sA[(r + g + 8) * PAD + kk + tg + 4];
            }
#pragma unroll
            for (int nf = 0; nf < 4; nf++) {
                int r = wn + (nf << 3);
                bf[nf][0] = sB[(r + g) * PAD + kk + tg];
                bf[nf][1] = sB[(r + g) * PAD + kk + tg + 4];
            }
#pragma unroll
            for (int mf = 0; mf < 4; mf++)
#pragma unroll
                for (int nf = 0; nf < 4; nf++)
                    asm volatile(
                        "mma.sync.aligned.m16n8k16.row.col.f32.f16.f16.f32 "
                        "{%0,%1,%2,%3}, {%4,%5,%6,%7}, {%8,%9}, {%0,%1,%2,%3};"
                        : "+f"(acc[mf][nf][0]), "+f"(acc[mf][nf][1]),
                          "+f"(acc[mf][nf][2]), "+f"(acc[mf][nf][3])
                        : "r"(af[mf][0]), "r"(af[mf][1]),
                          "r"(af[mf][2]), "r"(af[mf][3]),
                          "r"(bf[nf][0]), "r"(bf[nf][1]));
        }
        __syncthreads();
        if (++stage == 3) stage = 0;
    }

#pragma unroll
    for (int mf = 0; mf < 4; mf++) {
        int r0 = m0 + wm + (mf << 4) + g;
#pragma unroll
        for (int nf = 0; nf < 4; nf++) {
            int col = n0 + wn + (nf << 3) + (tg << 1);
            if (!NBOUND || col < N) {   // col even, N even -> pair safe
                float bv0 = 0.0f, bv1 = 0.0f;
                if (bias1) { bv0 += bias1[col]; bv1 += bias1[col + 1]; }
                if (bias2) { bv0 += bias2[col]; bv1 += bias2[col + 1]; }
                float2 v0 = make_float2(acc[mf][nf][0] + bv0, acc[mf][nf][1] + bv1);
                float2 v1 = make_float2(acc[mf][nf][2] + bv0, acc[mf][nf][3] + bv1);
                *(float2*)(C + (long)r0 * N + col)       = v0;
                *(float2*)(C + (long)(r0 + 8) * N + col) = v1;
            }
        }
    }
}

// ---------------- kernel 3: persistent RNN + fused pooling (work stealing) ----
// Reads COMPACTED fp32 E; writes fp16 outpu. W_hh row tid in 128 registers.
__global__ void __launch_bounds__(128, 2)
rnn_pool_kernel(const float* __restrict__ E, const float* __restrict__ W_hh,
                const float* __restrict__ w, const float* __restrict__ wsum,
                const float* __restrict__ h0,
                const float* __restrict__ W_user, const int* __restrict__ au,
                const int* __restrict__ perm, const int* __restrict__ slen,
                const int* __restrict__ off,
                int* __restrict__ ctr,
                __half* __restrict__ outpu_h)
{
    __shared__ float hp[2 * GNB * 128];
    __shared__ float wst[2 * GNB];
    __shared__ int   s_grp;

    int tid = threadIdx.x;

    float4 wreg[32];
#pragma unroll
    for (int j4 = 0; j4 < 32; j4++)
        wreg[j4] = *(const float4*)(W_hh + (size_t)tid * 128 + j4 * 4);

    while (true) {
        __syncthreads();
        if (tid == 0) s_grp = atomicAdd(ctr, 1);
        __syncthreads();
        int grp = s_grp;
        if (grp >= NGRP) break;

        int j0 = grp * GNB;
        int r0 = perm[j0 + 0];
        int r1 = perm[j0 + 1];
        int r2 = perm[j0 + 2];
        int r3 = perm[j0 + 3];
        int stop = slen[j0];               // descending => max of group

        hp[0 * 128 + tid] = h0[(size_t)r0 * 128 + tid];
        hp[1 * 128 + tid] = h0[(size_t)r1 * 128 + tid];
        hp[2 * 128 + tid] = h0[(size_t)r2 * 128 + tid];
        hp[3 * 128 + tid] = h0[(size_t)r3 * 128 + tid];
        if (tid < GNB) wst[tid] = w[(size_t)0 * BATCH + perm[j0 + tid]];

        int base = off[0];
        float e0 = E[((size_t)base + j0 + 0) * 128 + tid];
        float e1 = E[((size_t)base + j0 + 1) * 128 + tid];
        float e2 = E[((size_t)base + j0 + 2) * 128 + tid];
        float e3 = E[((size_t)base + j0 + 3) * 128 + tid];

        float acc0 = 0.0f, acc1 = 0.0f, acc2 = 0.0f, acc3 = 0.0f;
        __syncthreads();

        int cur = 0;
        for (int s = 0; s < stop; s++) {
            float p0 = e0, p1 = e1, p2 = e2, p3 = e3;

            if (s + 1 < stop) {            // prefetch next step (clamped rows masked by w=0)
                int b2 = off[s + 1];
                int c2 = off[s + 2] - b2;
                int k0 = b2 + j0;
                int k1 = b2 + min(j0 + 1, c2 - 1);
                int k2 = b2 + min(j0 + 2, c2 - 1);
                int k3 = b2 + min(j0 + 3, c2 - 1);
                e0 = E[(size_t)k0 * 128 + tid];
                e1 = E[(size_t)k1 * 128 + tid];
                e2 = E[(size_t)k2 * 128 + tid];
                e3 = E[(size_t)k3 * 128 + tid];
                if (tid < GNB)
                    wst[((s + 1) & 1) * GNB + tid] =
                        w[(size_t)(s + 1) * BATCH + perm[j0 + tid]];
            }

            const float* hc = hp + cur * GNB * 128;
#pragma unroll
            for (int j4 = 0; j4 < 32; j4++) {
                float4 w4 = wreg[j4];
                float4 ha = *(const float4*)(hc + 0 * 128 + j4 * 4);
                float4 hb = *(const float4*)(hc + 1 * 128 + j4 * 4);
                float4 hcv = *(const float4*)(hc + 2 * 128 + j4 * 4);
                float4 hd = *(const float4*)(hc + 3 * 128 + j4 * 4);
                p0 = fmaf(ha.x, w4.x, p0); p0 = fmaf(ha.y, w4.y, p0);
                p0 = fmaf(ha.z, w4.z, p0); p0 = fmaf(ha.w, w4.w, p0);
                p1 = fmaf(hb.x, w4.x, p1); p1 = fmaf(hb.y, w4.y, p1);
                p1 = fmaf(hb.z, w4.z, p1); p1 = fmaf(hb.w, w4.w, p1);
                p2 = fmaf(hcv.x, w4.x, p2); p2 = fmaf(hcv.y, w4.y, p2);
                p2 = fmaf(hcv.z, w4.z, p2); p2 = fmaf(hcv.w, w4.w, p2);
                p3 = fmaf(hd.x, w4.x, p3); p3 = fmaf(hd.y, w4.y, p3);
                p3 = fmaf(hd.z, w4.z, p3); p3 = fmaf(hd.w, w4.w, p3);
            }

            float* hn = hp + (cur ^ 1) * GNB * 128;
            float ex, hv;
            ex = __expf(2.0f * p0); hv = 1.0f - __fdividef(2.0f, ex + 1.0f);
            hn[0 * 128 + tid] = hv; acc0 = fmaf(wst[(s & 1) * GNB + 0], hv, acc0);
            ex = __expf(2.0f * p1); hv = 1.0f - __fdividef(2.0f, ex + 1.0f);
            hn[1 * 128 + tid] = hv; acc1 = fmaf(wst[(s & 1) * GNB + 1], hv, acc1);
            ex = __expf(2.0f * p2); hv = 1.0f - __fdividef(2.0f, ex + 1.0f);
            hn[2 * 128 + tid] = hv; acc2 = fmaf(wst[(s & 1) * GNB + 2], hv, acc2);
            ex = __expf(2.0f * p3); hv = 1.0f - __fdividef(2.0f, ex + 1.0f);
            hn[3 * 128 + tid] = hv; acc3 = fmaf(wst[(s & 1) * GNB + 3], hv, acc3);

            cur ^= 1;
            __syncthreads();
        }

        outpu_h[(size_t)r0 * 256 + tid] = __float2half_rn(acc0 * (1.0f / wsum[r0]));
        outpu_h[(size_t)r1 * 256 + tid] = __float2half_rn(acc1 * (1.0f / wsum[r1]));
        outpu_h[(size_t)r2 * 256 + tid] = __float2half_rn(acc2 * (1.0f / wsum[r2]));
        outpu_h[(size_t)r3 * 256 + tid] = __float2half_rn(acc3 * (1.0f / wsum[r3]));
        outpu_h[(size_t)r0 * 256 + 128 + tid] = __float2half_rn(W_user[(size_t)au[r0] * 128 + tid]);
        outpu_h[(size_t)r1 * 256 + 128 + tid] = __float2half_rn(W_user[(size_t)au[r1] * 128 + tid]);
        outpu_h[(size_t)r2 * 256 + 128 + tid] = __float2half_rn(W_user[(size_t)au[r2] * 128 + tid]);
        outpu_h[(size_t)r3 * 256 + 128 + tid] = __float2half_rn(W_user[(size_t)au[r3] * 128 + tid]);
    }
}

// ---------------- launch ----------------
extern "C" void kernel_launch(void* const* d_in, const int* in_sizes, int n_in,
                              void* d_out, int out_size)
{
    const int*   x      = (const int*)  d_in[0];
    const float* t      = (const float*)d_in[1];
    const float* sxy    = (const float*)d_in[2];
    const float* h0     = (const float*)d_in[5];
    const int*   au     = (const int*)  d_in[6];
    const int*   len    = (const int*)  d_in[7];
    const float* W_enc  = (const float*)d_in[8];
    const float* W_user = (const float*)d_in[9];
    const float* W_ih   = (const float*)d_in[10];
    const float* W_hh   = (const float*)d_in[11];
    const float* b_ih   = (const float*)d_in[12];
    const float* b_hh   = (const float*)d_in[13];
    const float* W_fc   = (const float*)d_in[14];
    const float* b_fc   = (const float*)d_in[15];
    float* out = (float*)d_out;

    float *E, *w, *wsum;
    uint32_t *outpu_h, *Wenc_h, *Wih_h, *Wfc_h;
    int *perm, *slen, *ctr, *off, *Mpad, *gidx;
    cudaGetSymbolAddress((void**)&E,       g_E);
    cudaGetSymbolAddress((void**)&w,       g_w);
    cudaGetSymbolAddress((void**)&wsum,    g_wsum);
    cudaGetSymbolAddress((void**)&outpu_h, g_outpu_h);
    cudaGetSymbolAddress((void**)&Wenc_h,  g_Wenc_h);
    cudaGetSymbolAddress((void**)&Wih_h,   g_Wih_h);
    cudaGetSymbolAddress((void**)&Wfc_h,   g_Wfc_h);
    cudaGetSymbolAddress((void**)&perm,    g_perm);
    cudaGetSymbolAddress((void**)&slen,    g_slen);
    cudaGetSymbolAddress((void**)&ctr,     g_ctr);
    cudaGetSymbolAddress((void**)&off,     g_off);
    cudaGetSymbolAddress((void**)&Mpad,    g_Mpad);
    cudaGetSymbolAddress((void**)&gidx,    g_gidx);

    int gemm_smem = 6 * 128 * 20 * (int)sizeof(uint32_t);   // 61440 B (3-stage fp16)
    cudaFuncSetAttribute(gemm_f16<true, false>,
                         cudaFuncAttributeMaxDynamicSharedMemorySize, gemm_smem);
    cudaFuncSetAttribute(gemm_f16<false, true>,
                         cudaFuncAttributeMaxDynamicSharedMemorySize, gemm_smem);

    // 0) weight converts (fp16); length sort; compact-row metadata
    {
        int n4 = VOCAB * HID / 4;
        cvt_fp16_kernel<<<(n4 + 255) / 256, 256>>>((const float4*)W_enc,
                                                   (uint2*)Wenc_h, n4);
        n4 = HID * HID / 4;
        cvt_fp16_kernel<<<(n4 + 255) / 256, 256>>>((const float4*)W_ih,
                                                   (uint2*)Wih_h, n4);
        n4 = VOCAB * 2 * HID / 4;
        cvt_fp16_kernel<<<(n4 + 255) / 256, 256>>>((const float4*)W_fc,
                                                   (uint2*)Wfc_h, n4);
        sort_len_kernel<<<1, 1024>>>(len, perm, slen, ctr);
        build_offsets_kernel<<<1, 256>>>(slen, off, Mpad);
        fill_gidx_kernel<<<S_LEN + 1, 256>>>(x, perm, off, Mpad, gidx);
    }

    // 1) pooling weights
    pool_weights_kernel<<<BATCH, 256>>>(t, sxy, len, w, wsum);

    // 2) E_c = gather(Wenc_h, gidx) @ Wih_h^T + biases (compacted rows; CTAs
    //    past device-side Mpad exit immediately — fixed grid, capture-safe)
    dim3 gproj(S_LEN * BATCH / 128, 1);
    gemm_f16<true, false><<<gproj, 256, gemm_smem>>>(Wenc_h, gidx, Mpad, Wih_h,
                                                     b_ih, b_hh, E, HID, HID);

    // 3) persistent RNN + fused pooling, length-sorted work stealing
    rnn_pool_kernel<<<296, 128>>>(E, W_hh, w, wsum, h0, W_user, au,
                                  perm, slen, off, ctr, (__half*)outpu_h);

    // 4) logits = outpu @ Wfc_h^T + b_fc   (M=1024, N=100000, K=256)
    //    grid.x = m (fastest): the 8 CTAs sharing a W_fc tile are coscheduled.
    dim3 gfin(BATCH / 128, (VOCAB + 127) / 128);
    gemm_f16<false, true><<<gfin, 256, gemm_smem>>>(outpu_h, nullptr, nullptr,
                                                    Wfc_h, b_fc, nullptr, out,
                                                    VOCAB, 2 * HID);
}

// round 12
// speedup vs baseline: 1.1050x; 1.1050x over previous
#include <cuda_runtime.h>
#include <cuda_fp16.h>
#include <cstdint>

#define S_LEN 200
#define BATCH 1024
#define HID   128
#define VOCAB 100000
#define GNB   4          // batch rows per RNN work group
#define NGRP  (BATCH / GNB)

// ---------------- scratch (device globals; no allocation) ----------------
__device__ __align__(16) float    g_E[(size_t)S_LEN * BATCH * HID];   // compacted E (fp32)
__device__ __align__(16) float    g_w[(size_t)S_LEN * BATCH];
__device__ float                  g_wsum[BATCH];
__device__ __align__(16) uint32_t g_outpu_h[(size_t)BATCH * HID];     // fp16x2 [B,256]
__device__ __align__(16) uint32_t g_Wenc_h[(size_t)VOCAB * HID / 2];  // 25.6 MB fp16
__device__ __align__(16) uint32_t g_Wih_h[(size_t)HID * HID / 2];
__device__ __align__(16) uint32_t g_Wfc_h[(size_t)VOCAB * HID];       // 51.2 MB fp16 (V x 256)
__device__ int                    g_perm[BATCH];   // batch order, length descending
__device__ int                    g_slen[BATCH];   // sorted lengths
__device__ int                    g_ctr;           // work-steal counter
__device__ int                    g_off[S_LEN + 1];// compact row offsets
__device__ int                    g_Mpad;          // padded compact row count
__device__ int                    g_gidx[(size_t)S_LEN * BATCH]; // vocab id per compact row

// ---------------- helpers ----------------
__device__ __forceinline__ void cp16(void* smem, const void* gmem)
{
    uint32_t s = (uint32_t)__cvta_generic_to_shared(smem);
    asm volatile("cp.async.cg.shared.global [%0], [%1], 16;" :: "r"(s), "l"(gmem));
}
__device__ __forceinline__ void cp_commit() { asm volatile("cp.async.commit_group;"); }
template <int W> __device__ __forceinline__ void cp_wait()
{
    asm volatile("cp.async.wait_group %0;" :: "n"(W));
}
__device__ __forceinline__ uint32_t f2h2(float lo, float hi)
{
    __half2 h = __floats2half2_rn(lo, hi);   // lo -> low 16 bits
    return *(uint32_t*)&h;
}
__device__ __forceinline__ unsigned long long pack2(float x)
{
    unsigned long long r;
    asm("mov.b64 %0, {%1, %1};" : "=l"(r) : "f"(x));
    return r;
}
__device__ __forceinline__ unsigned long long packpair(float lo, float hi)
{
    unsigned long long r;
    asm("mov.b64 %0, {%1, %2};" : "=l"(r) : "f"(lo), "f"(hi));
    return r;
}
__device__ __forceinline__ void unpack2(unsigned long long v, float& lo, float& hi)
{
    asm("mov.b64 {%0, %1}, %2;" : "=f"(lo), "=f"(hi) : "l"(v));
}
__device__ __forceinline__ void ffma2(unsigned long long& d, unsigned long long a,
                                      unsigned long long b)
{
    asm("fma.rn.f32x2 %0, %1, %2, %0;" : "+l"(d) : "l"(a), "l"(b));
}

// ---------------- kernel 0: fp32 -> fp16 (RN) streaming convert -----------------
__global__ void cvt_fp16_kernel(const float4* __restrict__ in,
                                uint2* __restrict__ out, int n4)
{
    int i = blockIdx.x * blockDim.x + threadIdx.x;
    if (i < n4) {
        float4 v = in[i];
        out[i] = make_uint2(f2h2(v.x, v.y), f2h2(v.z, v.w));
    }
}

// ---------------- kernel 0b: sort batch rows by length (descending) ------------
__global__ void __launch_bounds__(1024)
sort_len_kernel(const int* __restrict__ length,
                int* __restrict__ perm, int* __restrict__ slen, int* __restrict__ ctr)
{
    __shared__ unsigned key[BATCH];
    int tid = threadIdx.x;
    key[tid] = ((unsigned)(200 - length[tid]) << 10) | (unsigned)tid;
    if (tid == 0) *ctr = 0;
    __syncthreads();
#pragma unroll 1
    for (int k = 2; k <= BATCH; k <<= 1) {
#pragma unroll 1
        for (int j = k >> 1; j > 0; j >>= 1) {
            int ixj = tid ^ j;
            if (ixj > tid) {
                unsigned a = key[tid], b = key[ixj];
                bool up = ((tid & k) == 0);
                if ((a > b) == up) { key[tid] = b; key[ixj] = a; }
            }
            __syncthreads();
        }
    }
    perm[tid] = (int)(key[tid] & 1023u);
    slen[tid] = 200 - (int)(key[tid] >> 10);
}

// ---------------- kernel 0c: compact-row offsets (1 small CTA) -----------------
__global__ void __launch_bounds__(256)
build_offsets_kernel(const int* __restrict__ slen, int* __restrict__ off,
                     int* __restrict__ Mpad)
{
    __shared__ int cnt[S_LEN];
    int s = threadIdx.x;
    if (s < S_LEN) {
        int lo = 0, hi = BATCH;           // count of slen[j] > s (sorted desc)
        while (lo < hi) { int mid = (lo + hi) >> 1; if (slen[mid] > s) lo = mid + 1; else hi = mid; }
        cnt[s] = lo;
    }
    __syncthreads();
    if (s == 0) {
        int acc = 0;
        for (int i = 0; i < S_LEN; i++) { off[i] = acc; acc += cnt[i]; }
        off[S_LEN] = acc;
        *Mpad = (acc + 127) & ~127;
    }
}

// ---------------- kernel 0d: fill gather indices for compacted rows ------------
__global__ void __launch_bounds__(256)
fill_gidx_kernel(const int* __restrict__ x, const int* __restrict__ perm,
                 const int* __restrict__ off, const int* __restrict__ Mpad,
                 int* __restrict__ gidx)
{
    int s = blockIdx.x;
    if (s < S_LEN) {
        int base = off[s], cnt = off[s + 1] - base;
        for (int j = threadIdx.x; j < cnt; j += blockDim.x)
            gidx[base + j] = x[(size_t)s * BATCH + perm[j]];
    } else {
        int total = off[S_LEN], mp = *Mpad;
        for (int i = threadIdx.x; i < mp - total; i += blockDim.x)
            gidx[total + i] = 0;
    }
}

// ---------------- kernel 1: pooling weights (1 block per batch, s-parallel) ----
__global__ void __launch_bounds__(256)
pool_weights_kernel(const float* __restrict__ t,
                    const float* __restrict__ sxy,
                    const int* __restrict__ length,
                    float* __restrict__ w,
                    float* __restrict__ wsum)
{
    int b   = blockIdx.x;
    int s   = threadIdx.x;
    int lane = s & 31, warp = s >> 5;
    __shared__ float red[8];
    __shared__ float bc[3];

    int len = length[b];
    if (s == 0) {
        bc[0] = t[(size_t)(len - 1) * BATCH + b];
        float2 sl = *(const float2*)&sxy[((size_t)(len - 1) * BATCH + b) * 2];
        bc[1] = sl.x;
        bc[2] = sl.y;
    }
    __syncthreads();

    const float c1 = 6.28318530717958647692f / 86400.0f;
    const float c2 = 0.1f / 86400.0f;
    float wv = 0.0f;
    if (s < S_LEN) {
        float dt = bc[0] - t[(size_t)s * BATCH + b];
        float2 sv = *(const float2*)&sxy[((size_t)s * BATCH + b) * 2];
        float dx = bc[1] - sv.x, dy = bc[2] - sv.y;
        float ds = sqrtf(dx * dx + dy * dy);
        float ft = (cosf(dt * c1) + 1.0f) * 0.5f * expf(-dt * c2);
        float fs = expf(-ds * 1000.0f);
        wv = (s < len) ? (ft * fs + 1e-10f) : 0.0f;
        w[(size_t)s * BATCH + b] = wv;
    }
#pragma unroll
    for (int off = 16; off > 0; off >>= 1)
        wv += __shfl_down_sync(0xffffffffu, wv, off);
    if (lane == 0) red[warp] = wv;
    __syncthreads();
    if (s < 8) {
        float v = red[s];
#pragma unroll
        for (int off = 4; off > 0; off >>= 1)
            v += __shfl_down_sync(0xffu, v, off);
        if (s == 0) wsum[b] = v;
    }
}

// ---------------- kernel 2/4: fp16 GEMM  C[M,N] = A[M,K]*B[N,K]^T + bias -------
// (unchanged from R11 — known good)
template <bool GATHER, bool NBOUND>
__global__ void __launch_bounds__(256, 2)
gemm_f16(const uint32_t* __restrict__ A, const int* __restrict__ gidx,
         const int* __restrict__ dM,
         const uint32_t* __restrict__ Bm,
         const float* __restrict__ bias1, const float* __restrict__ bias2,
         float* __restrict__ C, int N, int K)
{
    if (GATHER && (blockIdx.x << 7) >= *dM) return;

    const int PAD = 20;
    const int STG = 128 * PAD;
    extern __shared__ uint32_t smemu[];
    uint32_t* sAs = smemu;
    uint32_t* sBs = smemu + 3 * STG;

    int tid  = threadIdx.x;
    int lane = tid & 31, warp = tid >> 5;
    int wm = (warp & 1) << 6;
    int wn = (warp >> 1) << 5;
    int g  = lane >> 2, tg = lane & 3;
    int m0 = blockIdx.x * 128;
    int n0 = blockIdx.y * 128;

    int K2 = K >> 1;
    int lrow = tid >> 2;
    int lc4  = (tid & 3) << 2;

    float acc[4][4][4];
#pragma unroll
    for (int a = 0; a < 4; a++)
#pragma unroll
        for (int b = 0; b < 4; b++)
#pragma unroll
            for (int c = 0; c < 4; c++) acc[a][b][c] = 0.0f;

    auto load_tile = [&](int stage, int k0u) {
#pragma unroll
        for (int q = 0; q < 2; q++) {
            int r = q * 64 + lrow;
            long arow = GATHER ? (long)gidx[m0 + r] : (long)(m0 + r);
            cp16(sAs + stage * STG + r * PAD + lc4, A + arow * (long)K2 + k0u + lc4);
            int nrow = n0 + r;
            if (NBOUND && nrow >= N) nrow = N - 1;
            cp16(sBs + stage * STG + r * PAD + lc4, Bm + (long)nrow * K2 + k0u + lc4);
        }
        cp_commit();
    };

    int nChunks = K >> 5;
    load_tile(0, 0);
    if (nChunks > 1) load_tile(1, 16);

    int stage = 0;
    for (int kc = 0; kc < nChunks; kc++) {
        if (kc + 1 < nChunks) cp_wait<1>(); else cp_wait<0>();
        __syncthreads();
        if (kc + 2 < nChunks) {
            int nst = stage + 2; if (nst >= 3) nst -= 3;
            load_tile(nst, (kc + 2) << 4);
        }

        const uint32_t* sA = sAs + stage * STG;
        const uint32_t* sB = sBs + stage * STG;
#pragma unroll
        for (int ks = 0; ks < 2; ks++) {
            int kk = ks << 3;
            uint32_t af[4][4];
            uint32_t bf[4][2];
#pragma unroll
            for (int mf = 0; mf < 4; mf++) {
                int r = wm + (mf << 4);
                af[mf][0] = sA[(r + g)     * PAD + kk + tg];
                af[mf][1] = sA[(r + g + 8) * PAD + kk + tg];
                af[mf][2] = sA[(r + g)     * PAD + kk + tg + 4];
                af[mf][3] = sA[(r + g + 8) * PAD + kk + tg + 4];
            }
#pragma unroll
            for (int nf = 0; nf < 4; nf++) {
                int r = wn + (nf << 3);
                bf[nf][0] = sB[(r + g) * PAD + kk + tg];
                bf[nf][1] = sB[(r + g) * PAD + kk + tg + 4];
            }
#pragma unroll
            for (int mf = 0; mf < 4; mf++)
#pragma unroll
                for (int nf = 0; nf < 4; nf++)
                    asm volatile(
                        "mma.sync.aligned.m16n8k16.row.col.f32.f16.f16.f32 "
                        "{%0,%1,%2,%3}, {%4,%5,%6,%7}, {%8,%9}, {%0,%1,%2,%3};"
                        : "+f"(acc[mf][nf][0]), "+f"(acc[mf][nf][1]),
                          "+f"(acc[mf][nf][2]), "+f"(acc[mf][nf][3])
                        : "r"(af[mf][0]), "r"(af[mf][1]),
                          "r"(af[mf][2]), "r"(af[mf][3]),
                          "r"(bf[nf][0]), "r"(bf[nf][1]));
        }
        __syncthreads();
        if (++stage == 3) stage = 0;
    }

#pragma unroll
    for (int mf = 0; mf < 4; mf++) {
        int r0 = m0 + wm + (mf << 4) + g;
#pragma unroll
        for (int nf = 0; nf < 4; nf++) {
            int col = n0 + wn + (nf << 3) + (tg << 1);
            if (!NBOUND || col < N) {
                float bv0 = 0.0f, bv1 = 0.0f;
                if (bias1) { bv0 += bias1[col]; bv1 += bias1[col + 1]; }
                if (bias2) { bv0 += bias2[col]; bv1 += bias2[col + 1]; }
                float2 v0 = make_float2(acc[mf][nf][0] + bv0, acc[mf][nf][1] + bv1);
                float2 v1 = make_float2(acc[mf][nf][2] + bv0, acc[mf][nf][3] + bv1);
                *(float2*)(C + (long)r0 * N + col)       = v0;
                *(float2*)(C + (long)(r0 + 8) * N + col) = v1;
            }
        }
    }
}

// ---------------- kernel 3: persistent RNN + fused pooling (FFMA2) ------------
// h layout hp[buf][unit j][4 rows] (float4): writer = 1 STS.128/thread,
// reader = LDS.128 broadcast -> two f32x2 lanes (rows {0,1},{2,3}).
// Per-unit fma order identical to R11 -> bit-identical results.
__global__ void __launch_bounds__(128, 2)
rnn_pool_kernel(const float* __restrict__ E, const float* __restrict__ W_hh,
                const float* __restrict__ w, const float* __restrict__ wsum,
                const float* __restrict__ h0,
                const float* __restrict__ W_user, const int* __restrict__ au,
                const int* __restrict__ perm, const int* __restrict__ slen,
                const int* __restrict__ off,
                int* __restrict__ ctr,
                __half* __restrict__ outpu_h)
{
    __shared__ __align__(16) float hp[2 * 128 * 4];   // [buf][unit][4 rows]
    __shared__ float wst[2 * GNB];
    __shared__ int   s_grp;

    int tid = threadIdx.x;

    float4 wreg[32];
#pragma unroll
    for (int j4 = 0; j4 < 32; j4++)
        wreg[j4] = *(const float4*)(W_hh + (size_t)tid * 128 + j4 * 4);

    while (true) {
        __syncthreads();
        if (tid == 0) s_grp = atomicAdd(ctr, 1);
        __syncthreads();
        int grp = s_grp;
        if (grp >= NGRP) break;

        int j0 = grp * GNB;
        int r0 = perm[j0 + 0];
        int r1 = perm[j0 + 1];
        int r2 = perm[j0 + 2];
        int r3 = perm[j0 + 3];
        int stop = slen[j0];               // descending => max of group

        // init: hp[0][tid] = {h_r0, h_r1, h_r2, h_r3}
        {
            float4 hi;
            hi.x = h0[(size_t)r0 * 128 + tid];
            hi.y = h0[(size_t)r1 * 128 + tid];
            hi.z = h0[(size_t)r2 * 128 + tid];
            hi.w = h0[(size_t)r3 * 128 + tid];
            *(float4*)(hp + tid * 4) = hi;
        }
        if (tid < GNB) wst[tid] = w[(size_t)0 * BATCH + perm[j0 + tid]];

        int base = off[0];
        float e0 = E[((size_t)base + j0 + 0) * 128 + tid];
        float e1 = E[((size_t)base + j0 + 1) * 128 + tid];
        float e2 = E[((size_t)base + j0 + 2) * 128 + tid];
        float e3 = E[((size_t)base + j0 + 3) * 128 + tid];

        float acc0 = 0.0f, acc1 = 0.0f, acc2 = 0.0f, acc3 = 0.0f;
        __syncthreads();

        int cur = 0;
        for (int s = 0; s < stop; s++) {
            unsigned long long p01 = packpair(e0, e1);
            unsigned long long p23 = packpair(e2, e3);

            if (s + 1 < stop) {            // prefetch next step (clamped rows masked by w=0)
                int b2 = off[s + 1];
                int c2 = off[s + 2] - b2;
                int k0 = b2 + j0;
                int k1 = b2 + min(j0 + 1, c2 - 1);
                int k2 = b2 + min(j0 + 2, c2 - 1);
                int k3 = b2 + min(j0 + 3, c2 - 1);
                e0 = E[(size_t)k0 * 128 + tid];
                e1 = E[(size_t)k1 * 128 + tid];
                e2 = E[(size_t)k2 * 128 + tid];
                e3 = E[(size_t)k3 * 128 + tid];
                if (tid < GNB)
                    wst[((s + 1) & 1) * GNB + tid] =
                        w[(size_t)(s + 1) * BATCH + perm[j0 + tid]];
            }

            const float* hc = hp + cur * 128 * 4;
#pragma unroll
            for (int j4 = 0; j4 < 32; j4++) {
                float4 w4 = wreg[j4];
#pragma unroll
                for (int jj = 0; jj < 4; jj++) {
                    float wv = (jj == 0) ? w4.x : (jj == 1) ? w4.y
                             : (jj == 2) ? w4.z : w4.w;
                    unsigned long long wp = pack2(wv);
                    float4 hv4 = *(const float4*)(hc + (j4 * 4 + jj) * 4); // broadcast
                    ulonglong2 hu = *(const ulonglong2*)&hv4;
                    ffma2(p01, wp, hu.x);   // rows 0,1
                    ffma2(p23, wp, hu.y);   // rows 2,3
                }
            }

            float pre0, pre1, pre2, pre3;
            unpack2(p01, pre0, pre1);
            unpack2(p23, pre2, pre3);

            float* hn = hp + (cur ^ 1) * 128 * 4;
            float ex, hva, hvb, hvc, hvd;
            ex = __expf(2.0f * pre0); hva = 1.0f - __fdividef(2.0f, ex + 1.0f);
            acc0 = fmaf(wst[(s & 1) * GNB + 0], hva, acc0);
            ex = __expf(2.0f * pre1); hvb = 1.0f - __fdividef(2.0f, ex + 1.0f);
            acc1 = fmaf(wst[(s & 1) * GNB + 1], hvb, acc1);
            ex = __expf(2.0f * pre2); hvc = 1.0f - __fdividef(2.0f, ex + 1.0f);
            acc2 = fmaf(wst[(s & 1) * GNB + 2], hvc, acc2);
            ex = __expf(2.0f * pre3); hvd = 1.0f - __fdividef(2.0f, ex + 1.0f);
            acc3 = fmaf(wst[(s & 1) * GNB + 3], hvd, acc3);
            *(float4*)(hn + tid * 4) = make_float4(hva, hvb, hvc, hvd);

            cur ^= 1;
            __syncthreads();
        }

        outpu_h[(size_t)r0 * 256 + tid] = __float2half_rn(acc0 * (1.0f / wsum[r0]));
        outpu_h[(size_t)r1 * 256 + tid] = __float2half_rn(acc1 * (1.0f / wsum[r1]));
        outpu_h[(size_t)r2 * 256 + tid] = __float2half_rn(acc2 * (1.0f / wsum[r2]));
        outpu_h[(size_t)r3 * 256 + tid] = __float2half_rn(acc3 * (1.0f / wsum[r3]));
        outpu_h[(size_t)r0 * 256 + 128 + tid] = __float2half_rn(W_user[(size_t)au[r0] * 128 + tid]);
        outpu_h[(size_t)r1 * 256 + 128 + tid] = __float2half_rn(W_user[(size_t)au[r1] * 128 + tid]);
        outpu_h[(size_t)r2 * 256 + 128 + tid] = __float2half_rn(W_user[(size_t)au[r2] * 128 + tid]);
        outpu_h[(size_t)r3 * 256 + 128 + tid] = __float2half_rn(W_user[(size_t)au[r3] * 128 + tid]);
    }
}

// ---------------- launch ----------------
extern "C" void kernel_launch(void* const* d_in, const int* in_sizes, int n_in,
                              void* d_out, int out_size)
{
    const int*   x      = (const int*)  d_in[0];
    const float* t      = (const float*)d_in[1];
    const float* sxy    = (const float*)d_in[2];
    const float* h0     = (const float*)d_in[5];
    const int*   au     = (const int*)  d_in[6];
    const int*   len    = (const int*)  d_in[7];
    const float* W_enc  = (const float*)d_in[8];
    const float* W_user = (const float*)d_in[9];
    const float* W_ih   = (const float*)d_in[10];
    const float* W_hh   = (const float*)d_in[11];
    const float* b_ih   = (const float*)d_in[12];
    const float* b_hh   = (const float*)d_in[13];
    const float* W_fc   = (const float*)d_in[14];
    const float* b_fc   = (const float*)d_in[15];
    float* out = (float*)d_out;

    float *E, *w, *wsum;
    uint32_t *outpu_h, *Wenc_h, *Wih_h, *Wfc_h;
    int *perm, *slen, *ctr, *off, *Mpad, *gidx;
    cudaGetSymbolAddress((void**)&E,       g_E);
    cudaGetSymbolAddress((void**)&w,       g_w);
    cudaGetSymbolAddress((void**)&wsum,    g_wsum);
    cudaGetSymbolAddress((void**)&outpu_h, g_outpu_h);
    cudaGetSymbolAddress((void**)&Wenc_h,  g_Wenc_h);
    cudaGetSymbolAddress((void**)&Wih_h,   g_Wih_h);
    cudaGetSymbolAddress((void**)&Wfc_h,   g_Wfc_h);
    cudaGetSymbolAddress((void**)&perm,    g_perm);
    cudaGetSymbolAddress((void**)&slen,    g_slen);
    cudaGetSymbolAddress((void**)&ctr,     g_ctr);
    cudaGetSymbolAddress((void**)&off,     g_off);
    cudaGetSymbolAddress((void**)&Mpad,    g_Mpad);
    cudaGetSymbolAddress((void**)&gidx,    g_gidx);

    int gemm_smem = 6 * 128 * 20 * (int)sizeof(uint32_t);   // 61440 B (3-stage fp16)
    cudaFuncSetAttribute(gemm_f16<true, false>,
                         cudaFuncAttributeMaxDynamicSharedMemorySize, gemm_smem);
    cudaFuncSetAttribute(gemm_f16<false, true>,
                         cudaFuncAttributeMaxDynamicSharedMemorySize, gemm_smem);

    // 0) weight converts (fp16); length sort; compact-row metadata
    {
        int n4 = VOCAB * HID / 4;
        cvt_fp16_kernel<<<(n4 + 255) / 256, 256>>>((const float4*)W_enc,
                                                   (uint2*)Wenc_h, n4);
        n4 = HID * HID / 4;
        cvt_fp16_kernel<<<(n4 + 255) / 256, 256>>>((const float4*)W_ih,
                                                   (uint2*)Wih_h, n4);
        n4 = VOCAB * 2 * HID / 4;
        cvt_fp16_kernel<<<(n4 + 255) / 256, 256>>>((const float4*)W_fc,
                                                   (uint2*)Wfc_h, n4);
        sort_len_kernel<<<1, 1024>>>(len, perm, slen, ctr);
        build_offsets_kernel<<<1, 256>>>(slen, off, Mpad);
        fill_gidx_kernel<<<S_LEN + 1, 256>>>(x, perm, off, Mpad, gidx);
    }

    // 1) pooling weights
    pool_weights_kernel<<<BATCH, 256>>>(t, sxy, len, w, wsum);

    // 2) E_c = gather(Wenc_h, gidx) @ Wih_h^T + biases (compacted rows)
    dim3 gproj(S_LEN * BATCH / 128, 1);
    gemm_f16<true, false><<<gproj, 256, gemm_smem>>>(Wenc_h, gidx, Mpad, Wih_h,
                                                     b_ih, b_hh, E, HID, HID);

    // 3) persistent RNN + fused pooling, length-sorted work stealing (FFMA2)
    rnn_pool_kernel<<<296, 128>>>(E, W_hh, w, wsum, h0, W_user, au,
                                  perm, slen, off, ctr, (__half*)outpu_h);

    // 4) logits = outpu @ Wfc_h^T + b_fc   (M=1024, N=100000, K=256)
    dim3 gfin(BATCH / 128, (VOCAB + 127) / 128);
    gemm_f16<false, true><<<gfin, 256, gemm_smem>>>(outpu_h, nullptr, nullptr,
                                                    Wfc_h, b_fc, nullptr, out,
                                                    VOCAB, 2 * HID);
}

// round 13
// speedup vs baseline: 1.1114x; 1.0058x over previous
#include <cuda_runtime.h>
#include <cuda_fp16.h>
#include <cstdint>

#define S_LEN 200
#define BATCH 1024
#define HID   128
#define VOCAB 100000
#define GNB   4          // batch rows per RNN work group
#define NGRP  (BATCH / GNB)

// ---------------- scratch (device globals; no allocation) ----------------
__device__ __align__(16) float    g_E[(size_t)S_LEN * BATCH * HID];   // compacted E (fp32)
__device__ __align__(16) float    g_w[(size_t)S_LEN * BATCH];
__device__ float                  g_wsum[BATCH];
__device__ __align__(16) uint32_t g_outpu_h[(size_t)BATCH * HID];     // fp16x2 [B,256]
__device__ __align__(16) uint32_t g_Wenc_h[(size_t)VOCAB * HID / 2];  // 25.6 MB fp16
__device__ __align__(16) uint32_t g_Wih_h[(size_t)HID * HID / 2];
__device__ __align__(16) uint32_t g_Wfc_h[(size_t)VOCAB * HID];       // 51.2 MB fp16 (V x 256)
__device__ int                    g_perm[BATCH];   // batch order, length descending
__device__ int                    g_slen[BATCH];   // sorted lengths
__device__ int                    g_ctr;           // work-steal counter
__device__ int                    g_off[S_LEN + 1];// compact row offsets
__device__ int                    g_Mpad;          // padded compact row count
__device__ int                    g_gidx[(size_t)S_LEN * BATCH]; // vocab id per compact row

// ---------------- helpers ----------------
__device__ __forceinline__ void cp16(void* smem, const void* gmem)
{
    uint32_t s = (uint32_t)__cvta_generic_to_shared(smem);
    asm volatile("cp.async.cg.shared.global [%0], [%1], 16;" :: "r"(s), "l"(gmem));
}
__device__ __forceinline__ void cp_commit() { asm volatile("cp.async.commit_group;"); }
template <int W> __device__ __forceinline__ void cp_wait()
{
    asm volatile("cp.async.wait_group %0;" :: "n"(W));
}
__device__ __forceinline__ uint32_t f2h2(float lo, float hi)
{
    __half2 h = __floats2half2_rn(lo, hi);   // lo -> low 16 bits
    return *(uint32_t*)&h;
}
__device__ __forceinline__ unsigned long long pack2(float x)
{
    unsigned long long r;
    asm("mov.b64 %0, {%1, %1};" : "=l"(r) : "f"(x));
    return r;
}
__device__ __forceinline__ unsigned long long packpair(float lo, float hi)
{
    unsigned long long r;
    asm("mov.b64 %0, {%1, %2};" : "=l"(r) : "f"(lo), "f"(hi));
    return r;
}
__device__ __forceinline__ void unpack2(unsigned long long v, float& lo, float& hi)
{
    asm("mov.b64 {%0, %1}, %2;" : "=f"(lo), "=f"(hi) : "l"(v));
}
__device__ __forceinline__ void ffma2(unsigned long long& d, unsigned long long a,
                                      unsigned long long b)
{
    asm("fma.rn.f32x2 %0, %1, %2, %0;" : "+l"(d) : "l"(a), "l"(b));
}

// ---------------- kernel 0: fp32 -> fp16 (RN) streaming convert -----------------
__global__ void cvt_fp16_kernel(const float4* __restrict__ in,
                                uint2* __restrict__ out, int n4)
{
    int i = blockIdx.x * blockDim.x + threadIdx.x;
    if (i < n4) {
        float4 v = in[i];
        out[i] = make_uint2(f2h2(v.x, v.y), f2h2(v.z, v.w));
    }
}

// ---------------- kernel 0b: sort batch rows by length (descending) ------------
__global__ void __launch_bounds__(1024)
sort_len_kernel(const int* __restrict__ length,
                int* __restrict__ perm, int* __restrict__ slen, int* __restrict__ ctr)
{
    __shared__ unsigned key[BATCH];
    int tid = threadIdx.x;
    key[tid] = ((unsigned)(200 - length[tid]) << 10) | (unsigned)tid;
    if (tid == 0) *ctr = 0;
    __syncthreads();
#pragma unroll 1
    for (int k = 2; k <= BATCH; k <<= 1) {
#pragma unroll 1
        for (int j = k >> 1; j > 0; j >>= 1) {
            int ixj = tid ^ j;
            if (ixj > tid) {
                unsigned a = key[tid], b = key[ixj];
                bool up = ((tid & k) == 0);
                if ((a > b) == up) { key[tid] = b; key[ixj] = a; }
            }
            __syncthreads();
        }
    }
    perm[tid] = (int)(key[tid] & 1023u);
    slen[tid] = 200 - (int)(key[tid] >> 10);
}

// ---------------- kernel 0c: compact-row offsets (1 small CTA) -----------------
__global__ void __launch_bounds__(256)
build_offsets_kernel(const int* __restrict__ slen, int* __restrict__ off,
                     int* __restrict__ Mpad)
{
    __shared__ int cnt[S_LEN];
    int s = threadIdx.x;
    if (s < S_LEN) {
        int lo = 0, hi = BATCH;           // count of slen[j] > s (sorted desc)
        while (lo < hi) { int mid = (lo + hi) >> 1; if (slen[mid] > s) lo = mid + 1; else hi = mid; }
        cnt[s] = lo;
    }
    __syncthreads();
    if (s == 0) {
        int acc = 0;
        for (int i = 0; i < S_LEN; i++) { off[i] = acc; acc += cnt[i]; }
        off[S_LEN] = acc;
        *Mpad = (acc + 127) & ~127;
    }
}

// ---------------- kernel 0d: fill gather indices for compacted rows ------------
__global__ void __launch_bounds__(256)
fill_gidx_kernel(const int* __restrict__ x, const int* __restrict__ perm,
                 const int* __restrict__ off, const int* __restrict__ Mpad,
                 int* __restrict__ gidx)
{
    int s = blockIdx.x;
    if (s < S_LEN) {
        int base = off[s], cnt = off[s + 1] - base;
        for (int j = threadIdx.x; j < cnt; j += blockDim.x)
            gidx[base + j] = x[(size_t)s * BATCH + perm[j]];
    } else {
        int total = off[S_LEN], mp = *Mpad;
        for (int i = threadIdx.x; i < mp - total; i += blockDim.x)
            gidx[total + i] = 0;
    }
}

// ---------------- kernel 1: pooling weights (1 block per batch, s-parallel) ----
__global__ void __launch_bounds__(256)
pool_weights_kernel(const float* __restrict__ t,
                    const float* __restrict__ sxy,
                    const int* __restrict__ length,
                    float* __restrict__ w,
                    float* __restrict__ wsum)
{
    int b   = blockIdx.x;
    int s   = threadIdx.x;
    int lane = s & 31, warp = s >> 5;
    __shared__ float red[8];
    __shared__ float bc[3];

    int len = length[b];
    if (s == 0) {
        bc[0] = t[(size_t)(len - 1) * BATCH + b];
        float2 sl = *(const float2*)&sxy[((size_t)(len - 1) * BATCH + b) * 2];
        bc[1] = sl.x;
        bc[2] = sl.y;
    }
    __syncthreads();

    const float c1 = 6.28318530717958647692f / 86400.0f;
    const float c2 = 0.1f / 86400.0f;
    float wv = 0.0f;
    if (s < S_LEN) {
        float dt = bc[0] - t[(size_t)s * BATCH + b];
        float2 sv = *(const float2*)&sxy[((size_t)s * BATCH + b) * 2];
        float dx = bc[1] - sv.x, dy = bc[2] - sv.y;
        float ds = sqrtf(dx * dx + dy * dy);
        float ft = (cosf(dt * c1) + 1.0f) * 0.5f * expf(-dt * c2);
        float fs = expf(-ds * 1000.0f);
        wv = (s < len) ? (ft * fs + 1e-10f) : 0.0f;
        w[(size_t)s * BATCH + b] = wv;
    }
#pragma unroll
    for (int off = 16; off > 0; off >>= 1)
        wv += __shfl_down_sync(0xffffffffu, wv, off);
    if (lane == 0) red[warp] = wv;
    __syncthreads();
    if (s < 8) {
        float v = red[s];
#pragma unroll
        for (int off = 4; off > 0; off >>= 1)
            v += __shfl_down_sync(0xffu, v, off);
        if (s == 0) wsum[b] = v;
    }
}

// ---------------- kernel 2/4: fp16 GEMM  C[M,N] = A[M,K]*B[N,K]^T + bias -------
// A,B PRE-CONVERTED fp16 (u32 = f16x2 along k). 3-stage cp.async with ONE
// barrier per chunk (stage kc+2 == stage kc-1 whose readers passed this
// iteration's leading sync). 256 threads, 8 warps 2(m)x4(n), mma m16n8k16.
// NBOUND also selects streaming (.cs) epilogue stores.
template <bool GATHER, bool NBOUND>
__global__ void __launch_bounds__(256, 2)
gemm_f16(const uint32_t* __restrict__ A, const int* __restrict__ gidx,
         const int* __restrict__ dM,
         const uint32_t* __restrict__ Bm,
         const float* __restrict__ bias1, const float* __restrict__ bias2,
         float* __restrict__ C, int N, int K)
{
    if (GATHER && (blockIdx.x << 7) >= *dM) return;

    const int PAD = 20;
    const int STG = 128 * PAD;
    extern __shared__ uint32_t smemu[];
    uint32_t* sAs = smemu;
    uint32_t* sBs = smemu + 3 * STG;

    int tid  = threadIdx.x;
    int lane = tid & 31, warp = tid >> 5;
    int wm = (warp & 1) << 6;
    int wn = (warp >> 1) << 5;
    int g  = lane >> 2, tg = lane & 3;
    int m0 = blockIdx.x * 128;
    int n0 = blockIdx.y * 128;

    int K2 = K >> 1;
    int lrow = tid >> 2;
    int lc4  = (tid & 3) << 2;

    float acc[4][4][4];
#pragma unroll
    for (int a = 0; a < 4; a++)
#pragma unroll
        for (int b = 0; b < 4; b++)
#pragma unroll
            for (int c = 0; c < 4; c++) acc[a][b][c] = 0.0f;

    auto load_tile = [&](int stage, int k0u) {
#pragma unroll
        for (int q = 0; q < 2; q++) {
            int r = q * 64 + lrow;
            long arow = GATHER ? (long)gidx[m0 + r] : (long)(m0 + r);
            cp16(sAs + stage * STG + r * PAD + lc4, A + arow * (long)K2 + k0u + lc4);
            int nrow = n0 + r;
            if (NBOUND && nrow >= N) nrow = N - 1;
            cp16(sBs + stage * STG + r * PAD + lc4, Bm + (long)nrow * K2 + k0u + lc4);
        }
        cp_commit();
    };

    int nChunks = K >> 5;
    load_tile(0, 0);
    if (nChunks > 1) load_tile(1, 16);

    int stage = 0;
    for (int kc = 0; kc < nChunks; kc++) {
        if (kc + 1 < nChunks) cp_wait<1>(); else cp_wait<0>();
        __syncthreads();     // single barrier: data ready + stage kc-1 free
        if (kc + 2 < nChunks) {
            int nst = stage + 2; if (nst >= 3) nst -= 3;
            load_tile(nst, (kc + 2) << 4);
        }

        const uint32_t* sA = sAs + stage * STG;
        const uint32_t* sB = sBs + stage * STG;
#pragma unroll
        for (int ks = 0; ks < 2; ks++) {
            int kk = ks << 3;
            uint32_t af[4][4];
            uint32_t bf[4][2];
#pragma unroll
            for (int mf = 0; mf < 4; mf++) {
                int r = wm + (mf << 4);
                af[mf][0] = sA[(r + g)     * PAD + kk + tg];
                af[mf][1] = sA[(r + g + 8) * PAD + kk + tg];
                af[mf][2] = sA[(r + g)     * PAD + kk + tg + 4];
                af[mf][3] = sA[(r + g + 8) * PAD + kk + tg + 4];
            }
#pragma unroll
            for (int nf = 0; nf < 4; nf++) {
                int r = wn + (nf << 3);
                bf[nf][0] = sB[(r + g) * PAD + kk + tg];
                bf[nf][1] = sB[(r + g) * PAD + kk + tg + 4];
            }
#pragma unroll
            for (int mf = 0; mf < 4; mf++)
#pragma unroll
                for (int nf = 0; nf < 4; nf++)
                    asm volatile(
                        "mma.sync.aligned.m16n8k16.row.col.f32.f16.f16.f32 "
                        "{%0,%1,%2,%3}, {%4,%5,%6,%7}, {%8,%9}, {%0,%1,%2,%3};"
                        : "+f"(acc[mf][nf][0]), "+f"(acc[mf][nf][1]),
                          "+f"(acc[mf][nf][2]), "+f"(acc[mf][nf][3])
                        : "r"(af[mf][0]), "r"(af[mf][1]),
                          "r"(af[mf][2]), "r"(af[mf][3]),
                          "r"(bf[nf][0]), "r"(bf[nf][1]));
        }
        if (++stage == 3) stage = 0;
    }

#pragma unroll
    for (int mf = 0; mf < 4; mf++) {
        int r0 = m0 + wm + (mf << 4) + g;
#pragma unroll
        for (int nf = 0; nf < 4; nf++) {
            int col = n0 + wn + (nf << 3) + (tg << 1);
            if (!NBOUND || col < N) {
                float bv0 = 0.0f, bv1 = 0.0f;
                if (bias1) { bv0 += bias1[col]; bv1 += bias1[col + 1]; }
                if (bias2) { bv0 += bias2[col]; bv1 += bias2[col + 1]; }
                float2 v0 = make_float2(acc[mf][nf][0] + bv0, acc[mf][nf][1] + bv1);
                float2 v1 = make_float2(acc[mf][nf][2] + bv0, acc[mf][nf][3] + bv1);
                if (NBOUND) {   // streaming stores: output never re-read
                    __stcs((float2*)(C + (long)r0 * N + col), v0);
                    __stcs((float2*)(C + (long)(r0 + 8) * N + col), v1);
                } else {
                    *(float2*)(C + (long)r0 * N + col)       = v0;
                    *(float2*)(C + (long)(r0 + 8) * N + col) = v1;
                }
            }
        }
    }
}

// ---------------- kernel 3: persistent RNN + fused pooling (FFMA2) ------------
// (unchanged from R12 — known good)
__global__ void __launch_bounds__(128, 2)
rnn_pool_kernel(const float* __restrict__ E, const float* __restrict__ W_hh,
                const float* __restrict__ w, const float* __restrict__ wsum,
                const float* __restrict__ h0,
                const float* __restrict__ W_user, const int* __restrict__ au,
                const int* __restrict__ perm, const int* __restrict__ slen,
                const int* __restrict__ off,
                int* __restrict__ ctr,
                __half* __restrict__ outpu_h)
{
    __shared__ __align__(16) float hp[2 * 128 * 4];   // [buf][unit][4 rows]
    __shared__ float wst[2 * GNB];
    __shared__ int   s_grp;

    int tid = threadIdx.x;

    float4 wreg[32];
#pragma unroll
    for (int j4 = 0; j4 < 32; j4++)
        wreg[j4] = *(const float4*)(W_hh + (size_t)tid * 128 + j4 * 4);

    while (true) {
        __syncthreads();
        if (tid == 0) s_grp = atomicAdd(ctr, 1);
        __syncthreads();
        int grp = s_grp;
        if (grp >= NGRP) break;

        int j0 = grp * GNB;
        int r0 = perm[j0 + 0];
        int r1 = perm[j0 + 1];
        int r2 = perm[j0 + 2];
        int r3 = perm[j0 + 3];
        int stop = slen[j0];               // descending => max of group

        {
            float4 hi;
            hi.x = h0[(size_t)r0 * 128 + tid];
            hi.y = h0[(size_t)r1 * 128 + tid];
            hi.z = h0[(size_t)r2 * 128 + tid];
            hi.w = h0[(size_t)r3 * 128 + tid];
            *(float4*)(hp + tid * 4) = hi;
        }
        if (tid < GNB) wst[tid] = w[(size_t)0 * BATCH + perm[j0 + tid]];

        int base = off[0];
        float e0 = E[((size_t)base + j0 + 0) * 128 + tid];
        float e1 = E[((size_t)base + j0 + 1) * 128 + tid];
        float e2 = E[((size_t)base + j0 + 2) * 128 + tid];
        float e3 = E[((size_t)base + j0 + 3) * 128 + tid];

        float acc0 = 0.0f, acc1 = 0.0f, acc2 = 0.0f, acc3 = 0.0f;
        __syncthreads();

        int cur = 0;
        for (int s = 0; s < stop; s++) {
            unsigned long long p01 = packpair(e0, e1);
            unsigned long long p23 = packpair(e2, e3);

            if (s + 1 < stop) {            // prefetch next step (clamped rows masked by w=0)
                int b2 = off[s + 1];
                int c2 = off[s + 2] - b2;
                int k0 = b2 + j0;
                int k1 = b2 + min(j0 + 1, c2 - 1);
                int k2 = b2 + min(j0 + 2, c2 - 1);
                int k3 = b2 + min(j0 + 3, c2 - 1);
                e0 = E[(size_t)k0 * 128 + tid];
                e1 = E[(size_t)k1 * 128 + tid];
                e2 = E[(size_t)k2 * 128 + tid];
                e3 = E[(size_t)k3 * 128 + tid];
                if (tid < GNB)
                    wst[((s + 1) & 1) * GNB + tid] =
                        w[(size_t)(s + 1) * BATCH + perm[j0 + tid]];
            }

            const float* hc = hp + cur * 128 * 4;
#pragma unroll
            for (int j4 = 0; j4 < 32; j4++) {
                float4 w4 = wreg[j4];
#pragma unroll
                for (int jj = 0; jj < 4; jj++) {
                    float wv = (jj == 0) ? w4.x : (jj == 1) ? w4.y
                             : (jj == 2) ? w4.z : w4.w;
                    unsigned long long wp = pack2(wv);
                    float4 hv4 = *(const float4*)(hc + (j4 * 4 + jj) * 4); // broadcast
                    ulonglong2 hu = *(const ulonglong2*)&hv4;
                    ffma2(p01, wp, hu.x);   // rows 0,1
                    ffma2(p23, wp, hu.y);   // rows 2,3
                }
            }

            float pre0, pre1, pre2, pre3;
            unpack2(p01, pre0, pre1);
            unpack2(p23, pre2, pre3);

            float* hn = hp + (cur ^ 1) * 128 * 4;
            float ex, hva, hvb, hvc, hvd;
            ex = __expf(2.0f * pre0); hva = 1.0f - __fdividef(2.0f, ex + 1.0f);
            acc0 = fmaf(wst[(s & 1) * GNB + 0], hva, acc0);
            ex = __expf(2.0f * pre1); hvb = 1.0f - __fdividef(2.0f, ex + 1.0f);
            acc1 = fmaf(wst[(s & 1) * GNB + 1], hvb, acc1);
            ex = __expf(2.0f * pre2); hvc = 1.0f - __fdividef(2.0f, ex + 1.0f);
            acc2 = fmaf(wst[(s & 1) * GNB + 2], hvc, acc2);
            ex = __expf(2.0f * pre3); hvd = 1.0f - __fdividef(2.0f, ex + 1.0f);
            acc3 = fmaf(wst[(s & 1) * GNB + 3], hvd, acc3);
            *(float4*)(hn + tid * 4) = make_float4(hva, hvb, hvc, hvd);

            cur ^= 1;
            __syncthreads();
        }

        outpu_h[(size_t)r0 * 256 + tid] = __float2half_rn(acc0 * (1.0f / wsum[r0]));
        outpu_h[(size_t)r1 * 256 + tid] = __float2half_rn(acc1 * (1.0f / wsum[r1]));
        outpu_h[(size_t)r2 * 256 + tid] = __float2half_rn(acc2 * (1.0f / wsum[r2]));
        outpu_h[(size_t)r3 * 256 + tid] = __float2half_rn(acc3 * (1.0f / wsum[r3]));
        outpu_h[(size_t)r0 * 256 + 128 + tid] = __float2half_rn(W_user[(size_t)au[r0] * 128 + tid]);
        outpu_h[(size_t)r1 * 256 + 128 + tid] = __float2half_rn(W_user[(size_t)au[r1] * 128 + tid]);
        outpu_h[(size_t)r2 * 256 + 128 + tid] = __float2half_rn(W_user[(size_t)au[r2] * 128 + tid]);
        outpu_h[(size_t)r3 * 256 + 128 + tid] = __float2half_rn(W_user[(size_t)au[r3] * 128 + tid]);
    }
}

// ---------------- launch ----------------
extern "C" void kernel_launch(void* const* d_in, const int* in_sizes, int n_in,
                              void* d_out, int out_size)
{
    const int*   x      = (const int*)  d_in[0];
    const float* t      = (const float*)d_in[1];
    const float* sxy    = (const float*)d_in[2];
    const float* h0     = (const float*)d_in[5];
    const int*   au     = (const int*)  d_in[6];
    const int*   len    = (const int*)  d_in[7];
    const float* W_enc  = (const float*)d_in[8];
    const float* W_user = (const float*)d_in[9];
    const float* W_ih   = (const float*)d_in[10];
    const float* W_hh   = (const float*)d_in[11];
    const float* b_ih   = (const float*)d_in[12];
    const float* b_hh   = (const float*)d_in[13];
    const float* W_fc   = (const float*)d_in[14];
    const float* b_fc   = (const float*)d_in[15];
    float* out = (float*)d_out;

    float *E, *w, *wsum;
    uint32_t *outpu_h, *Wenc_h, *Wih_h, *Wfc_h;
    int *perm, *slen, *ctr, *off, *Mpad, *gidx;
    cudaGetSymbolAddress((void**)&E,       g_E);
    cudaGetSymbolAddress((void**)&w,       g_w);
    cudaGetSymbolAddress((void**)&wsum,    g_wsum);
    cudaGetSymbolAddress((void**)&outpu_h, g_outpu_h);
    cudaGetSymbolAddress((void**)&Wenc_h,  g_Wenc_h);
    cudaGetSymbolAddress((void**)&Wih_h,   g_Wih_h);
    cudaGetSymbolAddress((void**)&Wfc_h,   g_Wfc_h);
    cudaGetSymbolAddress((void**)&perm,    g_perm);
    cudaGetSymbolAddress((void**)&slen,    g_slen);
    cudaGetSymbolAddress((void**)&ctr,     g_ctr);
    cudaGetSymbolAddress((void**)&off,     g_off);
    cudaGetSymbolAddress((void**)&Mpad,    g_Mpad);
    cudaGetSymbolAddress((void**)&gidx,    g_gidx);

    int gemm_smem = 6 * 128 * 20 * (int)sizeof(uint32_t);   // 61440 B (3-stage fp16)
    cudaFuncSetAttribute(gemm_f16<true, false>,
                         cudaFuncAttributeMaxDynamicSharedMemorySize, gemm_smem);
    cudaFuncSetAttribute(gemm_f16<false, true>,
                         cudaFuncAttributeMaxDynamicSharedMemorySize, gemm_smem);

    // ---- stream fork (capture-safe event-join pattern) ----
    cudaStream_t sB, sC;
    cudaStreamCreateWithFlags(&sB, cudaStreamNonBlocking);
    cudaStreamCreateWithFlags(&sC, cudaStreamNonBlocking);
    cudaEvent_t evRoot, evB, evC;
    cudaEventCreateWithFlags(&evRoot, cudaEventDisableTiming);
    cudaEventCreateWithFlags(&evB,    cudaEventDisableTiming);
    cudaEventCreateWithFlags(&evC,    cudaEventDisableTiming);

    cudaEventRecord(evRoot, 0);
    cudaStreamWaitEvent(sB, evRoot, 0);
    cudaStreamWaitEvent(sC, evRoot, 0);

    // stream B: W_fc convert (only needed by final GEMM — hidden behind proj+RNN)
    {
        int n4 = VOCAB * 2 * HID / 4;
        cvt_fp16_kernel<<<(n4 + 255) / 256, 256, 0, sB>>>((const float4*)W_fc,
                                                          (uint2*)Wfc_h, n4);
        cudaEventRecord(evB, sB);
    }

    // stream C: length sort -> offsets -> gidx ; pooling weights
    {
        sort_len_kernel<<<1, 1024, 0, sC>>>(len, perm, slen, ctr);
        build_offsets_kernel<<<1, 256, 0, sC>>>(slen, off, Mpad);
        fill_gidx_kernel<<<S_LEN + 1, 256, 0, sC>>>(x, perm, off, Mpad, gidx);
        pool_weights_kernel<<<BATCH, 256, 0, sC>>>(t, sxy, len, w, wsum);
        cudaEventRecord(evC, sC);
    }

    // main stream: W_enc / W_ih converts
    {
        int n4 = VOCAB * HID / 4;
        cvt_fp16_kernel<<<(n4 + 255) / 256, 256>>>((const float4*)W_enc,
                                                   (uint2*)Wenc_h, n4);
        n4 = HID * HID / 4;
        cvt_fp16_kernel<<<(n4 + 255) / 256, 256>>>((const float4*)W_ih,
                                                   (uint2*)Wih_h, n4);
    }

    // join C, then proj + RNN on main
    cudaStreamWaitEvent(0, evC, 0);
    dim3 gproj(S_LEN * BATCH / 128, 1);
    gemm_f16<true, false><<<gproj, 256, gemm_smem>>>(Wenc_h, gidx, Mpad, Wih_h,
                                                     b_ih, b_hh, E, HID, HID);

    rnn_pool_kernel<<<296, 128>>>(E, W_hh, w, wsum, h0, W_user, au,
                                  perm, slen, off, ctr, (__half*)outpu_h);

    // join B, then final GEMM
    cudaStreamWaitEvent(0, evB, 0);
    dim3 gfin(BATCH / 128, (VOCAB + 127) / 128);
    gemm_f16<false, true><<<gfin, 256, gemm_smem>>>(outpu_h, nullptr, nullptr,
                                                    Wfc_h, b_fc, nullptr, out,
                                                    VOCAB, 2 * HID);

    cudaStreamDestroy(sB);
    cudaStreamDestroy(sC);
}

// round 14
// speedup vs baseline: 1.2090x; 1.0878x over previous
#include <cuda_runtime.h>
#include <cuda_fp16.h>
#include <cstdint>

#define S_LEN 200
#define BATCH 1024
#define HID   128
#define VOCAB 100000
#define GNB   4          // batch rows per RNN work group
#define NGRP  (BATCH / GNB)

// ---------------- scratch (device globals; no allocation) ----------------
__device__ __align__(16) float    g_E[(size_t)S_LEN * BATCH * HID];   // compacted E (fp32)
__device__ __align__(16) float    g_w[(size_t)S_LEN * BATCH];
__device__ float                  g_wsum[BATCH];
__device__ __align__(16) uint32_t g_outpu_h[(size_t)BATCH * HID];     // fp16x2 [B,256]
__device__ __align__(16) uint32_t g_Wenc_h[(size_t)VOCAB * HID / 2];  // 25.6 MB fp16
__device__ __align__(16) uint32_t g_Wih_h[(size_t)HID * HID / 2];
__device__ __align__(16) uint32_t g_Wfc_h[(size_t)VOCAB * HID];       // 51.2 MB fp16 (V x 256)
__device__ int                    g_perm[BATCH];   // batch order, length descending
__device__ int                    g_slen[BATCH];   // sorted lengths
__device__ int                    g_ctr;           // work-steal counter
__device__ int                    g_off[S_LEN + 1];// compact row offsets
__device__ int                    g_Mpad;          // padded compact row count
__device__ int                    g_gidx[(size_t)S_LEN * BATCH]; // vocab id per compact row

// ---------------- helpers ----------------
__device__ __forceinline__ void cp16(void* smem, const void* gmem)
{
    uint32_t s = (uint32_t)__cvta_generic_to_shared(smem);
    asm volatile("cp.async.cg.shared.global [%0], [%1], 16;" :: "r"(s), "l"(gmem));
}
__device__ __forceinline__ void cp_commit() { asm volatile("cp.async.commit_group;"); }
template <int W> __device__ __forceinline__ void cp_wait()
{
    asm volatile("cp.async.wait_group %0;" :: "n"(W));
}
__device__ __forceinline__ uint32_t f2h2(float lo, float hi)
{
    __half2 h = __floats2half2_rn(lo, hi);   // lo -> low 16 bits
    return *(uint32_t*)&h;
}
__device__ __forceinline__ unsigned long long pack2(float x)
{
    unsigned long long r;
    asm("mov.b64 %0, {%1, %1};" : "=l"(r) : "f"(x));
    return r;
}
__device__ __forceinline__ unsigned long long packpair(float lo, float hi)
{
    unsigned long long r;
    asm("mov.b64 %0, {%1, %2};" : "=l"(r) : "f"(lo), "f"(hi));
    return r;
}
__device__ __forceinline__ void unpack2(unsigned long long v, float& lo, float& hi)
{
    asm("mov.b64 {%0, %1}, %2;" : "=f"(lo), "=f"(hi) : "l"(v));
}
__device__ __forceinline__ void ffma2(unsigned long long& d, unsigned long long a,
                                      unsigned long long b)
{
    asm("fma.rn.f32x2 %0, %1, %2, %0;" : "+l"(d) : "l"(a), "l"(b));
}

// ---------------- kernel 0: fp32 -> fp16 (RN) streaming convert -----------------
__global__ void cvt_fp16_kernel(const float4* __restrict__ in,
                                uint2* __restrict__ out, int n4)
{
    int i = blockIdx.x * blockDim.x + threadIdx.x;
    if (i < n4) {
        float4 v = in[i];
        out[i] = make_uint2(f2h2(v.x, v.y), f2h2(v.z, v.w));
    }
}

// ---------------- kernel 0b: sort batch rows by length (descending) ------------
__global__ void __launch_bounds__(1024)
sort_len_kernel(const int* __restrict__ length,
                int* __restrict__ perm, int* __restrict__ slen, int* __restrict__ ctr)
{
    __shared__ unsigned key[BATCH];
    int tid = threadIdx.x;
    key[tid] = ((unsigned)(200 - length[tid]) << 10) | (unsigned)tid;
    if (tid == 0) *ctr = 0;
    __syncthreads();
#pragma unroll 1
    for (int k = 2; k <= BATCH; k <<= 1) {
#pragma unroll 1
        for (int j = k >> 1; j > 0; j >>= 1) {
            int ixj = tid ^ j;
            if (ixj > tid) {
                unsigned a = key[tid], b = key[ixj];
                bool up = ((tid & k) == 0);
                if ((a > b) == up) { key[tid] = b; key[ixj] = a; }
            }
            __syncthreads();
        }
    }
    perm[tid] = (int)(key[tid] & 1023u);
    slen[tid] = 200 - (int)(key[tid] >> 10);
}

// ---------------- kernel 0c: compact-row offsets (1 small CTA) -----------------
__global__ void __launch_bounds__(256)
build_offsets_kernel(const int* __restrict__ slen, int* __restrict__ off,
                     int* __restrict__ Mpad)
{
    __shared__ int cnt[S_LEN];
    int s = threadIdx.x;
    if (s < S_LEN) {
        int lo = 0, hi = BATCH;           // count of slen[j] > s (sorted desc)
        while (lo < hi) { int mid = (lo + hi) >> 1; if (slen[mid] > s) lo = mid + 1; else hi = mid; }
        cnt[s] = lo;
    }
    __syncthreads();
    if (s == 0) {
        int acc = 0;
        for (int i = 0; i < S_LEN; i++) { off[i] = acc; acc += cnt[i]; }
        off[S_LEN] = acc;
        *Mpad = (acc + 127) & ~127;
    }
}

// ---------------- kernel 0d: fill gather indices for compacted rows ------------
__global__ void __launch_bounds__(256)
fill_gidx_kernel(const int* __restrict__ x, const int* __restrict__ perm,
                 const int* __restrict__ off, const int* __restrict__ Mpad,
                 int* __restrict__ gidx)
{
    int s = blockIdx.x;
    if (s < S_LEN) {
        int base = off[s], cnt = off[s + 1] - base;
        for (int j = threadIdx.x; j < cnt; j += blockDim.x)
            gidx[base + j] = x[(size_t)s * BATCH + perm[j]];
    } else {
        int total = off[S_LEN], mp = *Mpad;
        for (int i = threadIdx.x; i < mp - total; i += blockDim.x)
            gidx[total + i] = 0;
    }
}

// ---------------- kernel 1: pooling weights (1 block per batch, s-parallel) ----
__global__ void __launch_bounds__(256)
pool_weights_kernel(const float* __restrict__ t,
                    const float* __restrict__ sxy,
                    const int* __restrict__ length,
                    float* __restrict__ w,
                    float* __restrict__ wsum)
{
    int b   = blockIdx.x;
    int s   = threadIdx.x;
    int lane = s & 31, warp = s >> 5;
    __shared__ float red[8];
    __shared__ float bc[3];

    int len = length[b];
    if (s == 0) {
        bc[0] = t[(size_t)(len - 1) * BATCH + b];
        float2 sl = *(const float2*)&sxy[((size_t)(len - 1) * BATCH + b) * 2];
        bc[1] = sl.x;
        bc[2] = sl.y;
    }
    __syncthreads();

    const float c1 = 6.28318530717958647692f / 86400.0f;
    const float c2 = 0.1f / 86400.0f;
    float wv = 0.0f;
    if (s < S_LEN) {
        float dt = bc[0] - t[(size_t)s * BATCH + b];
        float2 sv = *(const float2*)&sxy[((size_t)s * BATCH + b) * 2];
        float dx = bc[1] - sv.x, dy = bc[2] - sv.y;
        float ds = sqrtf(dx * dx + dy * dy);
        float ft = (cosf(dt * c1) + 1.0f) * 0.5f * expf(-dt * c2);
        float fs = expf(-ds * 1000.0f);
        wv = (s < len) ? (ft * fs + 1e-10f) : 0.0f;
        w[(size_t)s * BATCH + b] = wv;
    }
#pragma unroll
    for (int off = 16; off > 0; off >>= 1)
        wv += __shfl_down_sync(0xffffffffu, wv, off);
    if (lane == 0) red[warp] = wv;
    __syncthreads();
    if (s < 8) {
        float v = red[s];
#pragma unroll
        for (int off = 4; off > 0; off >>= 1)
            v += __shfl_down_sync(0xffu, v, off);
        if (s == 0) wsum[b] = v;
    }
}

// ---------------- kernel 2/4: fp16 GEMM  C[M,N] = A[M,K]*B[N,K]^T + bias -------
// (unchanged from R13 — known good)
template <bool GATHER, bool NBOUND>
__global__ void __launch_bounds__(256, 2)
gemm_f16(const uint32_t* __restrict__ A, const int* __restrict__ gidx,
         const int* __restrict__ dM,
         const uint32_t* __restrict__ Bm,
         const float* __restrict__ bias1, const float* __restrict__ bias2,
         float* __restrict__ C, int N, int K)
{
    if (GATHER && (blockIdx.x << 7) >= *dM) return;

    const int PAD = 20;
    const int STG = 128 * PAD;
    extern __shared__ uint32_t smemu[];
    uint32_t* sAs = smemu;
    uint32_t* sBs = smemu + 3 * STG;

    int tid  = threadIdx.x;
    int lane = tid & 31, warp = tid >> 5;
    int wm = (warp & 1) << 6;
    int wn = (warp >> 1) << 5;
    int g  = lane >> 2, tg = lane & 3;
    int m0 = blockIdx.x * 128;
    int n0 = blockIdx.y * 128;

    int K2 = K >> 1;
    int lrow = tid >> 2;
    int lc4  = (tid & 3) << 2;

    float acc[4][4][4];
#pragma unroll
    for (int a = 0; a < 4; a++)
#pragma unroll
        for (int b = 0; b < 4; b++)
#pragma unroll
            for (int c = 0; c < 4; c++) acc[a][b][c] = 0.0f;

    auto load_tile = [&](int stage, int k0u) {
#pragma unroll
        for (int q = 0; q < 2; q++) {
            int r = q * 64 + lrow;
            long arow = GATHER ? (long)gidx[m0 + r] : (long)(m0 + r);
            cp16(sAs + stage * STG + r * PAD + lc4, A + arow * (long)K2 + k0u + lc4);
            int nrow = n0 + r;
            if (NBOUND && nrow >= N) nrow = N - 1;
            cp16(sBs + stage * STG + r * PAD + lc4, Bm + (long)nrow * K2 + k0u + lc4);
        }
        cp_commit();
    };

    int nChunks = K >> 5;
    load_tile(0, 0);
    if (nChunks > 1) load_tile(1, 16);

    int stage = 0;
    for (int kc = 0; kc < nChunks; kc++) {
        if (kc + 1 < nChunks) cp_wait<1>(); else cp_wait<0>();
        __syncthreads();     // single barrier: data ready + stage kc-1 free
        if (kc + 2 < nChunks) {
            int nst = stage + 2; if (nst >= 3) nst -= 3;
            load_tile(nst, (kc + 2) << 4);
        }

        const uint32_t* sA = sAs + stage * STG;
        const uint32_t* sB = sBs + stage * STG;
#pragma unroll
        for (int ks = 0; ks < 2; ks++) {
            int kk = ks << 3;
            uint32_t af[4][4];
            uint32_t bf[4][2];
#pragma unroll
            for (int mf = 0; mf < 4; mf++) {
                int r = wm + (mf << 4);
                af[mf][0] = sA[(r + g)     * PAD + kk + tg];
                af[mf][1] = sA[(r + g + 8) * PAD + kk + tg];
                af[mf][2] = sA[(r + g)     * PAD + kk + tg + 4];
                af[mf][3] = sA[(r + g + 8) * PAD + kk + tg + 4];
            }
#pragma unroll
            for (int nf = 0; nf < 4; nf++) {
                int r = wn + (nf << 3);
                bf[nf][0] = sB[(r + g) * PAD + kk + tg];
                bf[nf][1] = sB[(r + g) * PAD + kk + tg + 4];
            }
#pragma unroll
            for (int mf = 0; mf < 4; mf++)
#pragma unroll
                for (int nf = 0; nf < 4; nf++)
                    asm volatile(
                        "mma.sync.aligned.m16n8k16.row.col.f32.f16.f16.f32 "
                        "{%0,%1,%2,%3}, {%4,%5,%6,%7}, {%8,%9}, {%0,%1,%2,%3};"
                        : "+f"(acc[mf][nf][0]), "+f"(acc[mf][nf][1]),
                          "+f"(acc[mf][nf][2]), "+f"(acc[mf][nf][3])
                        : "r"(af[mf][0]), "r"(af[mf][1]),
                          "r"(af[mf][2]), "r"(af[mf][3]),
                          "r"(bf[nf][0]), "r"(bf[nf][1]));
        }
        if (++stage == 3) stage = 0;
    }

#pragma unroll
    for (int mf = 0; mf < 4; mf++) {
        int r0 = m0 + wm + (mf << 4) + g;
#pragma unroll
        for (int nf = 0; nf < 4; nf++) {
            int col = n0 + wn + (nf << 3) + (tg << 1);
            if (!NBOUND || col < N) {
                float bv0 = 0.0f, bv1 = 0.0f;
                if (bias1) { bv0 += bias1[col]; bv1 += bias1[col + 1]; }
                if (bias2) { bv0 += bias2[col]; bv1 += bias2[col + 1]; }
                float2 v0 = make_float2(acc[mf][nf][0] + bv0, acc[mf][nf][1] + bv1);
                float2 v1 = make_float2(acc[mf][nf][2] + bv0, acc[mf][nf][3] + bv1);
                if (NBOUND) {
                    __stcs((float2*)(C + (long)r0 * N + col), v0);
                    __stcs((float2*)(C + (long)(r0 + 8) * N + col), v1);
                } else {
                    *(float2*)(C + (long)r0 * N + col)       = v0;
                    *(float2*)(C + (long)(r0 + 8) * N + col) = v1;
                }
            }
        }
    }
}

// ---------------- kernel 3: persistent RNN, 256 threads, split-j reduction ----
// 148 CTAs (1/SM) x 256 threads. Thread (unit = tid&127, half = tid>>7).
// half h computes j in [64*half, 64*half+64). Upper half writes partial pair
// accumulators to smem; lower half combines, tanh, pools, stores h.
// Wall-group now gets a full SM's FMA pipe (~2x step rate vs R13).
__global__ void __launch_bounds__(256, 1)
rnn_pool_kernel(const float* __restrict__ E, const float* __restrict__ W_hh,
                const float* __restrict__ w, const float* __restrict__ wsum,
                const float* __restrict__ h0,
                const float* __restrict__ W_user, const int* __restrict__ au,
                const int* __restrict__ perm, const int* __restrict__ slen,
                const int* __restrict__ off,
                int* __restrict__ ctr,
                __half* __restrict__ outpu_h)
{
    __shared__ __align__(16) float hp[2 * 128 * 4];             // [buf][unit][4 rows]
    __shared__ __align__(16) unsigned long long psum[128][2];   // upper-half partials
    __shared__ float wst[2 * GNB];
    __shared__ int   s_grp;

    int tid  = threadIdx.x;
    int unit = tid & 127;
    int half = tid >> 7;            // 0: j 0..63, 1: j 64..127

    // W_hh row 'unit', this half's 64 weights -> 16 float4 regs
    float4 wreg[16];
#pragma unroll
    for (int j4 = 0; j4 < 16; j4++)
        wreg[j4] = *(const float4*)(W_hh + (size_t)unit * 128 + half * 64 + j4 * 4);

    while (true) {
        __syncthreads();
        if (tid == 0) s_grp = atomicAdd(ctr, 1);
        __syncthreads();
        int grp = s_grp;
        if (grp >= NGRP) break;

        int j0 = grp * GNB;
        int r0 = perm[j0 + 0];
        int r1 = perm[j0 + 1];
        int r2 = perm[j0 + 2];
        int r3 = perm[j0 + 3];
        int stop = slen[j0];               // descending => max of group

        float e0 = 0.f, e1 = 0.f, e2 = 0.f, e3 = 0.f;
        if (half == 0) {
            float4 hi;
            hi.x = h0[(size_t)r0 * 128 + unit];
            hi.y = h0[(size_t)r1 * 128 + unit];
            hi.z = h0[(size_t)r2 * 128 + unit];
            hi.w = h0[(size_t)r3 * 128 + unit];
            *(float4*)(hp + unit * 4) = hi;
            int base = off[0];
            e0 = E[((size_t)base + j0 + 0) * 128 + unit];
            e1 = E[((size_t)base + j0 + 1) * 128 + unit];
            e2 = E[((size_t)base + j0 + 2) * 128 + unit];
            e3 = E[((size_t)base + j0 + 3) * 128 + unit];
        }
        if (tid < GNB) wst[tid] = w[(size_t)0 * BATCH + perm[j0 + tid]];

        float acc0 = 0.0f, acc1 = 0.0f, acc2 = 0.0f, acc3 = 0.0f;
        __syncthreads();

        int cur = 0;
        for (int s = 0; s < stop; s++) {
            unsigned long long p01, p23;
            if (half == 0) { p01 = packpair(e0, e1); p23 = packpair(e2, e3); }
            else           { p01 = 0ull;             p23 = 0ull;             }

            if (half == 0 && s + 1 < stop) {   // prefetch next step (masked rows clamped)
                int b2 = off[s + 1];
                int c2 = off[s + 2] - b2;
                int k0 = b2 + j0;
                int k1 = b2 + min(j0 + 1, c2 - 1);
                int k2 = b2 + min(j0 + 2, c2 - 1);
                int k3 = b2 + min(j0 + 3, c2 - 1);
                e0 = E[(size_t)k0 * 128 + unit];
                e1 = E[(size_t)k1 * 128 + unit];
                e2 = E[(size_t)k2 * 128 + unit];
                e3 = E[(size_t)k3 * 128 + unit];
            }
            if (tid < GNB && s + 1 < stop)
                wst[((s + 1) & 1) * GNB + tid] =
                    w[(size_t)(s + 1) * BATCH + perm[j0 + tid]];

            const float* hc = hp + cur * 128 * 4 + half * 64 * 4;
#pragma unroll
            for (int j4 = 0; j4 < 16; j4++) {
                float4 w4 = wreg[j4];
#pragma unroll
                for (int jj = 0; jj < 4; jj++) {
                    float wv = (jj == 0) ? w4.x : (jj == 1) ? w4.y
                             : (jj == 2) ? w4.z : w4.w;
                    unsigned long long wp = pack2(wv);
                    float4 hv4 = *(const float4*)(hc + (j4 * 4 + jj) * 4); // broadcast
                    ulonglong2 hu = *(const ulonglong2*)&hv4;
                    ffma2(p01, wp, hu.x);   // rows 0,1
                    ffma2(p23, wp, hu.y);   // rows 2,3
                }
            }

            if (half == 1) {
                psum[unit][0] = p01;
                psum[unit][1] = p23;
            }
            __syncthreads();

            if (half == 0) {
                float pre0, pre1, pre2, pre3, q0, q1, q2, q3;
                unpack2(p01, pre0, pre1);
                unpack2(p23, pre2, pre3);
                unpack2(psum[unit][0], q0, q1);
                unpack2(psum[unit][1], q2, q3);
                pre0 += q0; pre1 += q1; pre2 += q2; pre3 += q3;

                float* hn = hp + (cur ^ 1) * 128 * 4;
                float ex, hva, hvb, hvc, hvd;
                ex = __expf(2.0f * pre0); hva = 1.0f - __fdividef(2.0f, ex + 1.0f);
                acc0 = fmaf(wst[(s & 1) * GNB + 0], hva, acc0);
                ex = __expf(2.0f * pre1); hvb = 1.0f - __fdividef(2.0f, ex + 1.0f);
                acc1 = fmaf(wst[(s & 1) * GNB + 1], hvb, acc1);
                ex = __expf(2.0f * pre2); hvc = 1.0f - __fdividef(2.0f, ex + 1.0f);
                acc2 = fmaf(wst[(s & 1) * GNB + 2], hvc, acc2);
                ex = __expf(2.0f * pre3); hvd = 1.0f - __fdividef(2.0f, ex + 1.0f);
                acc3 = fmaf(wst[(s & 1) * GNB + 3], hvd, acc3);
                *(float4*)(hn + unit * 4) = make_float4(hva, hvb, hvc, hvd);
            }
            cur ^= 1;
            __syncthreads();
        }

        if (half == 0) {
            outpu_h[(size_t)r0 * 256 + unit] = __float2half_rn(acc0 * (1.0f / wsum[r0]));
            outpu_h[(size_t)r1 * 256 + unit] = __float2half_rn(acc1 * (1.0f / wsum[r1]));
            outpu_h[(size_t)r2 * 256 + unit] = __float2half_rn(acc2 * (1.0f / wsum[r2]));
            outpu_h[(size_t)r3 * 256 + unit] = __float2half_rn(acc3 * (1.0f / wsum[r3]));
        } else {
            outpu_h[(size_t)r0 * 256 + 128 + unit] = __float2half_rn(W_user[(size_t)au[r0] * 128 + unit]);
            outpu_h[(size_t)r1 * 256 + 128 + unit] = __float2half_rn(W_user[(size_t)au[r1] * 128 + unit]);
            outpu_h[(size_t)r2 * 256 + 128 + unit] = __float2half_rn(W_user[(size_t)au[r2] * 128 + unit]);
            outpu_h[(size_t)r3 * 256 + 128 + unit] = __float2half_rn(W_user[(size_t)au[r3] * 128 + unit]);
        }
    }
}

// ---------------- launch ----------------
extern "C" void kernel_launch(void* const* d_in, const int* in_sizes, int n_in,
                              void* d_out, int out_size)
{
    const int*   x      = (const int*)  d_in[0];
    const float* t      = (const float*)d_in[1];
    const float* sxy    = (const float*)d_in[2];
    const float* h0     = (const float*)d_in[5];
    const int*   au     = (const int*)  d_in[6];
    const int*   len    = (const int*)  d_in[7];
    const float* W_enc  = (const float*)d_in[8];
    const float* W_user = (const float*)d_in[9];
    const float* W_ih   = (const float*)d_in[10];
    const float* W_hh   = (const float*)d_in[11];
    const float* b_ih   = (const float*)d_in[12];
    const float* b_hh   = (const float*)d_in[13];
    const float* W_fc   = (const float*)d_in[14];
    const float* b_fc   = (const float*)d_in[15];
    float* out = (float*)d_out;

    float *E, *w, *wsum;
    uint32_t *outpu_h, *Wenc_h, *Wih_h, *Wfc_h;
    int *perm, *slen, *ctr, *off, *Mpad, *gidx;
    cudaGetSymbolAddress((void**)&E,       g_E);
    cudaGetSymbolAddress((void**)&w,       g_w);
    cudaGetSymbolAddress((void**)&wsum,    g_wsum);
    cudaGetSymbolAddress((void**)&outpu_h, g_outpu_h);
    cudaGetSymbolAddress((void**)&Wenc_h,  g_Wenc_h);
    cudaGetSymbolAddress((void**)&Wih_h,   g_Wih_h);
    cudaGetSymbolAddress((void**)&Wfc_h,   g_Wfc_h);
    cudaGetSymbolAddress((void**)&perm,    g_perm);
    cudaGetSymbolAddress((void**)&slen,    g_slen);
    cudaGetSymbolAddress((void**)&ctr,     g_ctr);
    cudaGetSymbolAddress((void**)&off,     g_off);
    cudaGetSymbolAddress((void**)&Mpad,    g_Mpad);
    cudaGetSymbolAddress((void**)&gidx,    g_gidx);

    int gemm_smem = 6 * 128 * 20 * (int)sizeof(uint32_t);   // 61440 B (3-stage fp16)
    cudaFuncSetAttribute(gemm_f16<true, false>,
                         cudaFuncAttributeMaxDynamicSharedMemorySize, gemm_smem);
    cudaFuncSetAttribute(gemm_f16<false, true>,
                         cudaFuncAttributeMaxDynamicSharedMemorySize, gemm_smem);

    // ---- stream fork (capture-safe event-join pattern) ----
    cudaStream_t sB, sC;
    cudaStreamCreateWithFlags(&sB, cudaStreamNonBlocking);
    cudaStreamCreateWithFlags(&sC, cudaStreamNonBlocking);
    cudaEvent_t evRoot, evB, evC;
    cudaEventCreateWithFlags(&evRoot, cudaEventDisableTiming);
    cudaEventCreateWithFlags(&evB,    cudaEventDisableTiming);
    cudaEventCreateWithFlags(&evC,    cudaEventDisableTiming);

    cudaEventRecord(evRoot, 0);
    cudaStreamWaitEvent(sB, evRoot, 0);
    cudaStreamWaitEvent(sC, evRoot, 0);

    // stream B: W_fc convert (only needed by final GEMM)
    {
        int n4 = VOCAB * 2 * HID / 4;
        cvt_fp16_kernel<<<(n4 + 255) / 256, 256, 0, sB>>>((const float4*)W_fc,
                                                          (uint2*)Wfc_h, n4);
        cudaEventRecord(evB, sB);
    }

    // stream C: length sort -> offsets -> gidx ; pooling weights
    {
        sort_len_kernel<<<1, 1024, 0, sC>>>(len, perm, slen, ctr);
        build_offsets_kernel<<<1, 256, 0, sC>>>(slen, off, Mpad);
        fill_gidx_kernel<<<S_LEN + 1, 256, 0, sC>>>(x, perm, off, Mpad, gidx);
        pool_weights_kernel<<<BATCH, 256, 0, sC>>>(t, sxy, len, w, wsum);
        cudaEventRecord(evC, sC);
    }

    // main stream: W_enc / W_ih converts
    {
        int n4 = VOCAB * HID / 4;
        cvt_fp16_kernel<<<(n4 + 255) / 256, 256>>>((const float4*)W_enc,
                                                   (uint2*)Wenc_h, n4);
        n4 = HID * HID / 4;
        cvt_fp16_kernel<<<(n4 + 255) / 256, 256>>>((const float4*)W_ih,
                                                   (uint2*)Wih_h, n4);
    }

    // join C, then proj + RNN on main
    cudaStreamWaitEvent(0, evC, 0);
    dim3 gproj(S_LEN * BATCH / 128, 1);
    gemm_f16<true, false><<<gproj, 256, gemm_smem>>>(Wenc_h, gidx, Mpad, Wih_h,
                                                     b_ih, b_hh, E, HID, HID);

    rnn_pool_kernel<<<148, 256>>>(E, W_hh, w, wsum, h0, W_user, au,
                                  perm, slen, off, ctr, (__half*)outpu_h);

    // join B, then final GEMM
    cudaStreamWaitEvent(0, evB, 0);
    dim3 gfin(BATCH / 128, (VOCAB + 127) / 128);
    gemm_f16<false, true><<<gfin, 256, gemm_smem>>>(outpu_h, nullptr, nullptr,
                                                    Wfc_h, b_fc, nullptr, out,
                                                    VOCAB, 2 * HID);

    cudaStreamDestroy(sB);
    cudaStreamDestroy(sC);
}